// round 4
// baseline (speedup 1.0000x reference)
#include <cuda_runtime.h>
#include <cuda_bf16.h>
#include <cstdint>

#define N_NODES 50000
#define E_EDGES 800000
#define NHEAD 4
#define C 64
#define DIN 32
#define DOUT 128
#define HC 256   // NHEAD * C

// ---------------- device scratch (allocation-free rule: __device__ globals) ---------------
__device__ int   g_is64;
__device__ int   g_src[E_EDGES];
__device__ int   g_dst[E_EDGES];
__device__ float g_xl[N_NODES * HC];      // x @ Wl^T   [N,256]
__device__ float g_xr[N_NODES * HC];      // x @ Wr^T   [N,256]
__device__ float g_expv[E_EDGES * NHEAD]; // exp(logit) per edge,head
__device__ float g_denom[N_NODES * NHEAD];// softmax denominators
__device__ float g_deg[N_NODES];          // in-degree (counts dst)
__device__ float g_dinv[N_NODES];         // rsqrt(deg)
__device__ float g_accum[N_NODES * HC];   // GAT aggregate [N,H,C]
__device__ float g_h[N_NODES * C];        // elu(mean over heads) [N,64]
__device__ float g_agg[N_NODES * C];      // GCN-normalized aggregate [N,64]

// ---------------- K-1: detect index dtype --------------------------------------------------
// int64 data (values < 2^31) viewed as int32 = [lo0, 0, lo1, 0, ...]. Random int32 node ids
// in [0,50000) essentially never have 32 consecutive odd-position zeros.
__global__ void k_detect(const int* __restrict__ ei32) {
    if (threadIdx.x == 0 && blockIdx.x == 0) {
        int odd_zero = 1;
        for (int i = 1; i < 64; i += 2)
            if (ei32[i] != 0) { odd_zero = 0; break; }
        g_is64 = odd_zero;
    }
}

// ---------------- K-2: normalize indices to int32 ------------------------------------------
__global__ void k_convert(const void* __restrict__ ei) {
    int e = blockIdx.x * blockDim.x + threadIdx.x;
    if (e >= E_EDGES) return;
    if (g_is64) {
        const long long* p = (const long long*)ei;
        g_src[e] = (int)p[e];
        g_dst[e] = (int)p[E_EDGES + e];
    } else {
        const int* p = (const int*)ei;
        g_src[e] = p[e];
        g_dst[e] = p[E_EDGES + e];
    }
}

// ---------------- K0: zero the accumulators -----------------------------------------------
__global__ void k_zero() {
    int i = blockIdx.x * blockDim.x + threadIdx.x;
    int stride = gridDim.x * blockDim.x;
    for (int j = i; j < N_NODES * HC; j += stride) g_accum[j] = 0.0f;
    for (int j = i; j < N_NODES * C;  j += stride) g_agg[j]   = 0.0f;
    for (int j = i; j < N_NODES * NHEAD; j += stride) g_denom[j] = 0.0f;
    for (int j = i; j < N_NODES; j += stride) g_deg[j] = 0.0f;
}

// ---------------- K1: node linear  xl = x@Wl^T, xr = x@Wr^T  ------------------------------
__global__ void __launch_bounds__(256) k_node_linear(const float* __restrict__ x,
                                                     const float* __restrict__ Wl,
                                                     const float* __restrict__ Wr) {
    __shared__ float sx[8 * DIN];   // 1KB node tile
    int o = threadIdx.x;            // output column 0..255
    float wl[DIN], wr[DIN];
    #pragma unroll
    for (int k = 0; k < DIN; k++) {
        wl[k] = Wl[o * DIN + k];
        wr[k] = Wr[o * DIN + k];
    }
    for (int base = blockIdx.x * 8; base < N_NODES; base += gridDim.x * 8) {
        int nn = min(8, N_NODES - base);
        __syncthreads();
        for (int i = threadIdx.x; i < nn * DIN; i += blockDim.x)
            sx[i] = x[base * DIN + i];
        __syncthreads();
        for (int j = 0; j < nn; j++) {
            float al = 0.0f, ar = 0.0f;
            #pragma unroll
            for (int k = 0; k < DIN; k++) {
                float xv = sx[j * DIN + k];
                al += wl[k] * xv;
                ar += wr[k] * xv;
            }
            g_xl[(size_t)(base + j) * HC + o] = al;
            g_xr[(size_t)(base + j) * HC + o] = ar;
        }
    }
}

// ---------------- K2: edge attention logits + exp + denom + degree ------------------------
// warp per edge; lane l covers channels [8l, 8l+8) -> head = l/8.
__global__ void k_edge_att(const float* __restrict__ att) {
    __shared__ float satt[HC];
    if (threadIdx.x < HC) satt[threadIdx.x] = att[threadIdx.x];
    __syncthreads();
    int e = blockIdx.x * (blockDim.x >> 5) + (threadIdx.x >> 5);
    if (e >= E_EDGES) return;
    int l = threadIdx.x & 31;
    int src = g_src[e];
    int dst = g_dst[e];
    const float4* pl = (const float4*)(g_xl + (size_t)src * HC);
    const float4* pr = (const float4*)(g_xr + (size_t)dst * HC);
    float4 a0 = pl[2 * l], a1 = pl[2 * l + 1];
    float4 b0 = pr[2 * l], b1 = pr[2 * l + 1];
    const float* ap = satt + l * 8;
    float p = 0.0f, v;
    v = a0.x + b0.x; v = v > 0.0f ? v : 0.2f * v; p += v * ap[0];
    v = a0.y + b0.y; v = v > 0.0f ? v : 0.2f * v; p += v * ap[1];
    v = a0.z + b0.z; v = v > 0.0f ? v : 0.2f * v; p += v * ap[2];
    v = a0.w + b0.w; v = v > 0.0f ? v : 0.2f * v; p += v * ap[3];
    v = a1.x + b1.x; v = v > 0.0f ? v : 0.2f * v; p += v * ap[4];
    v = a1.y + b1.y; v = v > 0.0f ? v : 0.2f * v; p += v * ap[5];
    v = a1.z + b1.z; v = v > 0.0f ? v : 0.2f * v; p += v * ap[6];
    v = a1.w + b1.w; v = v > 0.0f ? v : 0.2f * v; p += v * ap[7];
    // reduce within each 8-lane head group
    p += __shfl_down_sync(0xffffffffu, p, 4, 8);
    p += __shfl_down_sync(0xffffffffu, p, 2, 8);
    p += __shfl_down_sync(0xffffffffu, p, 1, 8);
    if ((l & 7) == 0) {
        float ex = __expf(p);  // no max-subtraction: logits are O(10), safe in fp32
        g_expv[(size_t)e * NHEAD + (l >> 3)] = ex;
        atomicAdd(&g_denom[dst * NHEAD + (l >> 3)], ex);
    }
    if (l == 0) atomicAdd(&g_deg[dst], 1.0f);
}

// ---------------- K3: GAT message aggregation ---------------------------------------------
__global__ void k_edge_gat_agg() {
    int e = blockIdx.x * (blockDim.x >> 5) + (threadIdx.x >> 5);
    if (e >= E_EDGES) return;
    int l = threadIdx.x & 31;
    int src = g_src[e];
    int dst = g_dst[e];
    int h = l >> 3;
    float w = g_expv[(size_t)e * NHEAD + h] / (g_denom[dst * NHEAD + h] + 1e-16f);
    const float4* pl = (const float4*)(g_xl + (size_t)src * HC);
    float4 a0 = pl[2 * l], a1 = pl[2 * l + 1];
    float* dp = g_accum + (size_t)dst * HC + l * 8;
    atomicAdd(dp + 0, a0.x * w);
    atomicAdd(dp + 1, a0.y * w);
    atomicAdd(dp + 2, a0.z * w);
    atomicAdd(dp + 3, a0.w * w);
    atomicAdd(dp + 4, a1.x * w);
    atomicAdd(dp + 5, a1.y * w);
    atomicAdd(dp + 6, a1.z * w);
    atomicAdd(dp + 7, a1.w * w);
}

// ---------------- K4: head-mean + ELU ------------------------------------------------------
__global__ void k_elu_mean() {
    int i = blockIdx.x * blockDim.x + threadIdx.x;
    if (i >= N_NODES * C) return;
    int n = i >> 6, c = i & 63;
    const float* a = g_accum + (size_t)n * HC;
    float m = 0.25f * (a[c] + a[C + c] + a[2 * C + c] + a[3 * C + c]);
    g_h[i] = m > 0.0f ? m : expm1f(m);
}

// ---------------- K5: degree -> rsqrt ------------------------------------------------------
__global__ void k_dinv() {
    int n = blockIdx.x * blockDim.x + threadIdx.x;
    if (n < N_NODES) {
        float d = g_deg[n];
        g_dinv[n] = d > 0.0f ? rsqrtf(d) : 0.0f;
    }
}

// ---------------- K6: GCN aggregation in 64-dim (linear commuted past the sum) ------------
__global__ void k_edge_gcn() {
    int e = blockIdx.x * (blockDim.x >> 5) + (threadIdx.x >> 5);
    if (e >= E_EDGES) return;
    int l = threadIdx.x & 31;
    int src = g_src[e];
    int dst = g_dst[e];
    float norm = g_dinv[src] * g_dinv[dst];
    float2 v = ((const float2*)(g_h + (size_t)src * C))[l];
    float* dp = g_agg + (size_t)dst * C + 2 * l;
    atomicAdd(dp + 0, v.x * norm);
    atomicAdd(dp + 1, v.y * norm);
}

// ---------------- K7: final linear  out = agg @ Wg^T ---------------------------------------
__global__ void k_out_linear(const float* __restrict__ Wg, float* __restrict__ out) {
    __shared__ float sW[C * DOUT];  // 32KB (under 48KB static limit)
    __shared__ float sh[4 * C];
    for (int i = threadIdx.x; i < DOUT * C; i += blockDim.x) {
        int o = i / C, k = i % C;
        sW[k * DOUT + o] = Wg[i];
    }
    __syncthreads();
    int o = threadIdx.x;  // 0..127
    for (int base = blockIdx.x * 4; base < N_NODES; base += gridDim.x * 4) {
        int nn = min(4, N_NODES - base);
        for (int i = threadIdx.x; i < nn * C; i += blockDim.x)
            sh[i] = g_agg[(size_t)base * C + i];
        __syncthreads();
        for (int j = 0; j < nn; j++) {
            float s = 0.0f;
            #pragma unroll
            for (int k = 0; k < C; k++)
                s += sW[k * DOUT + o] * sh[j * C + k];
            out[(size_t)(base + j) * DOUT + o] = s;
        }
        __syncthreads();
    }
}

// ---------------- launch -------------------------------------------------------------------
extern "C" void kernel_launch(void* const* d_in, const int* in_sizes, int n_in,
                              void* d_out, int out_size) {
    const float* x   = (const float*)d_in[0];
    const void*  ei  = d_in[1];
    const float* Wl  = (const float*)d_in[2];
    const float* Wr  = (const float*)d_in[3];
    const float* att = (const float*)d_in[4];
    const float* Wg  = (const float*)d_in[5];
    float* out = (float*)d_out;
    (void)in_sizes; (void)n_in; (void)out_size;

    const int EDGE_BLOCKS = (E_EDGES + 7) / 8;  // warp-per-edge, 8 warps/block

    k_detect<<<1, 32>>>((const int*)ei);
    k_convert<<<(E_EDGES + 255) / 256, 256>>>(ei);
    k_zero<<<4096, 256>>>();
    k_node_linear<<<(N_NODES + 7) / 8, 256>>>(x, Wl, Wr);
    k_edge_att<<<EDGE_BLOCKS, 256>>>(att);
    k_dinv<<<(N_NODES + 255) / 256, 256>>>();
    k_edge_gat_agg<<<EDGE_BLOCKS, 256>>>();
    k_elu_mean<<<(N_NODES * C + 255) / 256, 256>>>();
    k_edge_gcn<<<EDGE_BLOCKS, 256>>>();
    k_out_linear<<<(N_NODES + 3) / 4, 128>>>(Wg, out);
}

// round 5
// speedup vs baseline: 3.9089x; 3.9089x over previous
#include <cuda_runtime.h>
#include <cuda_bf16.h>
#include <cstdint>

#define N_NODES 50000
#define E_EDGES 800000
#define NHEAD 4
#define C 64
#define DIN 32
#define DOUT 128
#define HC 256   // NHEAD * C

// ---------------- device scratch ----------------------------------------------------------
__device__ int   g_is64;
__device__ int   g_src[E_EDGES];
__device__ int   g_dst[E_EDGES];
__device__ float g_xl[N_NODES * HC];
__device__ float g_xr[N_NODES * HC];
__device__ float g_expv[E_EDGES * NHEAD];
__device__ float g_denom[N_NODES * NHEAD];
__device__ float g_deg[N_NODES];
__device__ float g_dinv[N_NODES];
__device__ float g_accum[N_NODES * HC];
__device__ float g_h[N_NODES * C];
__device__ float g_agg[N_NODES * C];

// ---------------- vector reductions (sm_90+) ----------------------------------------------
__device__ __forceinline__ void red_add_v4(float* p, float x, float y, float z, float w) {
    asm volatile("red.global.add.v4.f32 [%0], {%1,%2,%3,%4};"
                 :: "l"(p), "f"(x), "f"(y), "f"(z), "f"(w) : "memory");
}

// ---------------- K-1: detect index dtype --------------------------------------------------
__global__ void k_detect(const int* __restrict__ ei32) {
    if (threadIdx.x == 0 && blockIdx.x == 0) {
        int odd_zero = 1;
        for (int i = 1; i < 64; i += 2)
            if (ei32[i] != 0) { odd_zero = 0; break; }
        g_is64 = odd_zero;
    }
}

// ---------------- K-2: normalize indices to int32 ------------------------------------------
__global__ void k_convert(const void* __restrict__ ei) {
    int e = blockIdx.x * blockDim.x + threadIdx.x;
    if (e >= E_EDGES) return;
    if (g_is64) {
        const long long* p = (const long long*)ei;
        g_src[e] = (int)p[e];
        g_dst[e] = (int)p[E_EDGES + e];
    } else {
        const int* p = (const int*)ei;
        g_src[e] = p[e];
        g_dst[e] = p[E_EDGES + e];
    }
}

// ---------------- K0: zero accumulators ----------------------------------------------------
__global__ void k_zero() {
    int i = blockIdx.x * blockDim.x + threadIdx.x;
    int stride = gridDim.x * blockDim.x;
    for (int j = i; j < N_NODES * HC; j += stride) g_accum[j] = 0.0f;
    for (int j = i; j < N_NODES * C;  j += stride) g_agg[j]   = 0.0f;
    for (int j = i; j < N_NODES * NHEAD; j += stride) g_denom[j] = 0.0f;
    for (int j = i; j < N_NODES; j += stride) g_deg[j] = 0.0f;
}

// ---------------- K1: node linear ----------------------------------------------------------
// 256 threads; thread o owns output column o. Weights staged coalesced through padded smem
// into registers ONCE per block; grid-stride so only 1184 prologues total.
#define NL_TILE 16
__global__ void __launch_bounds__(256, 2) k_node_linear(const float* __restrict__ x,
                                                        const float* __restrict__ Wl,
                                                        const float* __restrict__ Wr) {
    __shared__ float sw[256 * 33];      // padded: bank-conflict-free column reads
    __shared__ float sx[NL_TILE * DIN]; // 2KB node tile
    int o = threadIdx.x;
    float wl[DIN], wr[DIN];
    for (int i = threadIdx.x; i < 256 * DIN; i += 256)
        sw[(i >> 5) * 33 + (i & 31)] = Wl[i];        // coalesced global read
    __syncthreads();
    #pragma unroll
    for (int k = 0; k < DIN; k++) wl[k] = sw[o * 33 + k];  // bank (o+k)%32: conflict-free
    __syncthreads();
    for (int i = threadIdx.x; i < 256 * DIN; i += 256)
        sw[(i >> 5) * 33 + (i & 31)] = Wr[i];
    __syncthreads();
    #pragma unroll
    for (int k = 0; k < DIN; k++) wr[k] = sw[o * 33 + k];

    for (int base = blockIdx.x * NL_TILE; base < N_NODES; base += gridDim.x * NL_TILE) {
        int nn = min(NL_TILE, N_NODES - base);
        __syncthreads();
        for (int i = threadIdx.x; i < nn * DIN; i += 256)
            sx[i] = x[base * DIN + i];
        __syncthreads();
        for (int j = 0; j < nn; j++) {
            const float4* sxv = (const float4*)(sx + j * DIN);
            float al = 0.0f, ar = 0.0f;
            #pragma unroll
            for (int q = 0; q < 8; q++) {
                float4 v = sxv[q];   // LDS.128 broadcast
                al += wl[4*q+0]*v.x + wl[4*q+1]*v.y + wl[4*q+2]*v.z + wl[4*q+3]*v.w;
                ar += wr[4*q+0]*v.x + wr[4*q+1]*v.y + wr[4*q+2]*v.z + wr[4*q+3]*v.w;
            }
            g_xl[(size_t)(base + j) * HC + o] = al;
            g_xr[(size_t)(base + j) * HC + o] = ar;
        }
    }
}

// ---------------- K2: edge attention -------------------------------------------------------
// warp per edge. Lane l owns channels [4l,4l+4) (head h0=l/16) and [128+4l,128+4l+4)
// (head h1=2+l/16) -> every gather instruction covers one dense 512B span.
__global__ void k_edge_att(const float* __restrict__ att) {
    __shared__ float satt[HC];
    if (threadIdx.x < HC) satt[threadIdx.x] = att[threadIdx.x];
    __syncthreads();
    int e = blockIdx.x * (blockDim.x >> 5) + (threadIdx.x >> 5);
    if (e >= E_EDGES) return;
    int l = threadIdx.x & 31;
    int src = g_src[e];
    int dst = g_dst[e];
    const float4* pl = (const float4*)(g_xl + (size_t)src * HC);
    const float4* pr = (const float4*)(g_xr + (size_t)dst * HC);
    float4 a0 = pl[l],      b0 = pr[l];        // channels 4l..4l+3
    float4 a1 = pl[32 + l], b1 = pr[32 + l];   // channels 128+4l..
    float p0 = 0.0f, p1 = 0.0f, v;
    v = a0.x + b0.x; v = v > 0.0f ? v : 0.2f * v; p0 += v * satt[4*l+0];
    v = a0.y + b0.y; v = v > 0.0f ? v : 0.2f * v; p0 += v * satt[4*l+1];
    v = a0.z + b0.z; v = v > 0.0f ? v : 0.2f * v; p0 += v * satt[4*l+2];
    v = a0.w + b0.w; v = v > 0.0f ? v : 0.2f * v; p0 += v * satt[4*l+3];
    v = a1.x + b1.x; v = v > 0.0f ? v : 0.2f * v; p1 += v * satt[128+4*l+0];
    v = a1.y + b1.y; v = v > 0.0f ? v : 0.2f * v; p1 += v * satt[128+4*l+1];
    v = a1.z + b1.z; v = v > 0.0f ? v : 0.2f * v; p1 += v * satt[128+4*l+2];
    v = a1.w + b1.w; v = v > 0.0f ? v : 0.2f * v; p1 += v * satt[128+4*l+3];
    // reduce over each 16-lane group (head h0 for p0, head h1 for p1)
    #pragma unroll
    for (int s = 8; s >= 1; s >>= 1) {
        p0 += __shfl_xor_sync(0xffffffffu, p0, s);
        p1 += __shfl_xor_sync(0xffffffffu, p1, s);
    }
    if ((l & 15) == 0) {
        int h = l >> 4;                 // 0 or 1
        float ex0 = __expf(p0);         // head h
        float ex1 = __expf(p1);         // head h+2
        g_expv[(size_t)e * NHEAD + h]     = ex0;
        g_expv[(size_t)e * NHEAD + 2 + h] = ex1;
        atomicAdd(&g_denom[dst * NHEAD + h],     ex0);
        atomicAdd(&g_denom[dst * NHEAD + 2 + h], ex1);
    }
    if (l == 0) atomicAdd(&g_deg[dst], 1.0f);
}

// ---------------- K3: GAT message aggregation (vec4 RED, dense spans) ----------------------
__global__ void k_edge_gat_agg() {
    int e = blockIdx.x * (blockDim.x >> 5) + (threadIdx.x >> 5);
    if (e >= E_EDGES) return;
    int l = threadIdx.x & 31;
    int src = g_src[e];
    int dst = g_dst[e];
    int h0 = l >> 4, h1 = 2 + (l >> 4);
    float w0 = g_expv[(size_t)e * NHEAD + h0] / (g_denom[dst * NHEAD + h0] + 1e-16f);
    float w1 = g_expv[(size_t)e * NHEAD + h1] / (g_denom[dst * NHEAD + h1] + 1e-16f);
    const float4* pl = (const float4*)(g_xl + (size_t)src * HC);
    float4 a0 = pl[l], a1 = pl[32 + l];
    float* dp = g_accum + (size_t)dst * HC;
    red_add_v4(dp + 4 * l,       a0.x * w0, a0.y * w0, a0.z * w0, a0.w * w0);
    red_add_v4(dp + 128 + 4 * l, a1.x * w1, a1.y * w1, a1.z * w1, a1.w * w1);
}

// ---------------- K4: head-mean + ELU ------------------------------------------------------
__global__ void k_elu_mean() {
    int i = blockIdx.x * blockDim.x + threadIdx.x;
    if (i >= N_NODES * C) return;
    int n = i >> 6, c = i & 63;
    const float* a = g_accum + (size_t)n * HC;
    float m = 0.25f * (a[c] + a[C + c] + a[2 * C + c] + a[3 * C + c]);
    g_h[i] = m > 0.0f ? m : expm1f(m);
}

// ---------------- K5: degree -> rsqrt ------------------------------------------------------
__global__ void k_dinv() {
    int n = blockIdx.x * blockDim.x + threadIdx.x;
    if (n < N_NODES) {
        float d = g_deg[n];
        g_dinv[n] = d > 0.0f ? rsqrtf(d) : 0.0f;
    }
}

// ---------------- K6: GCN aggregation, 2 edges per warp, vec4 RED --------------------------
__global__ void k_edge_gcn() {
    int warp = blockIdx.x * (blockDim.x >> 5) + (threadIdx.x >> 5);
    int l = threadIdx.x & 31;
    int e = warp * 2 + (l >> 4);
    if (e >= E_EDGES) return;
    int c4 = l & 15;                     // float4 index within the 64-float row
    int src = g_src[e];
    int dst = g_dst[e];
    float norm = g_dinv[src] * g_dinv[dst];
    float4 v = ((const float4*)(g_h + (size_t)src * C))[c4];
    red_add_v4(g_agg + (size_t)dst * C + 4 * c4,
               v.x * norm, v.y * norm, v.z * norm, v.w * norm);
}

// ---------------- K7: final linear ---------------------------------------------------------
// 128 threads; thread o owns output column o; Wg row in registers (staged via padded smem).
#define OL_TILE 8
__global__ void __launch_bounds__(128) k_out_linear(const float* __restrict__ Wg,
                                                    float* __restrict__ out) {
    __shared__ float sw[DOUT * 65];      // padded 33.3KB
    __shared__ float sh[OL_TILE * C];    // 2KB
    int o = threadIdx.x;
    float wg[C];
    for (int i = threadIdx.x; i < DOUT * C; i += 128)
        sw[(i >> 6) * 65 + (i & 63)] = Wg[i];        // coalesced
    __syncthreads();
    #pragma unroll
    for (int k = 0; k < C; k++) wg[k] = sw[o * 65 + k];  // conflict-free

    for (int base = blockIdx.x * OL_TILE; base < N_NODES; base += gridDim.x * OL_TILE) {
        int nn = min(OL_TILE, N_NODES - base);
        __syncthreads();
        for (int i = threadIdx.x; i < nn * C; i += 128)
            sh[i] = g_agg[(size_t)base * C + i];
        __syncthreads();
        for (int j = 0; j < nn; j++) {
            const float4* shv = (const float4*)(sh + j * C);
            float s = 0.0f;
            #pragma unroll
            for (int q = 0; q < 16; q++) {
                float4 v = shv[q];
                s += wg[4*q+0]*v.x + wg[4*q+1]*v.y + wg[4*q+2]*v.z + wg[4*q+3]*v.w;
            }
            out[(size_t)(base + j) * DOUT + o] = s;
        }
    }
}

// ---------------- launch -------------------------------------------------------------------
extern "C" void kernel_launch(void* const* d_in, const int* in_sizes, int n_in,
                              void* d_out, int out_size) {
    const float* x   = (const float*)d_in[0];
    const void*  ei  = d_in[1];
    const float* Wl  = (const float*)d_in[2];
    const float* Wr  = (const float*)d_in[3];
    const float* att = (const float*)d_in[4];
    const float* Wg  = (const float*)d_in[5];
    float* out = (float*)d_out;
    (void)in_sizes; (void)n_in; (void)out_size;

    const int EDGE_BLOCKS  = (E_EDGES + 7) / 8;       // warp-per-edge kernels
    const int EDGE_BLOCKS2 = (E_EDGES + 15) / 16;     // 2 edges/warp (gcn)

    k_detect<<<1, 32>>>((const int*)ei);
    k_convert<<<(E_EDGES + 255) / 256, 256>>>(ei);
    k_zero<<<1184, 256>>>();
    k_node_linear<<<1184, 256>>>(x, Wl, Wr);
    k_edge_att<<<EDGE_BLOCKS, 256>>>(att);
    k_dinv<<<(N_NODES + 255) / 256, 256>>>();
    k_edge_gat_agg<<<EDGE_BLOCKS, 256>>>();
    k_elu_mean<<<(N_NODES * C + 255) / 256, 256>>>();
    k_edge_gcn<<<EDGE_BLOCKS2, 256>>>();
    k_out_linear<<<592, 128>>>(Wg, out);
}

// round 6
// speedup vs baseline: 4.9296x; 1.2611x over previous
#include <cuda_runtime.h>
#include <cuda_bf16.h>
#include <cstdint>

#define N_NODES 50000
#define E_EDGES 800000
#define NHEAD 4
#define C 64
#define DIN 32
#define DOUT 128
#define HC 256   // NHEAD * C

// ---------------- device scratch ----------------------------------------------------------
__device__ int   g_is64;
__device__ int   g_src[E_EDGES];
__device__ int   g_dst[E_EDGES];
__device__ float g_xl[N_NODES * HC];
__device__ float g_xr[N_NODES * HC];
__device__ float g_denom[N_NODES * NHEAD];
__device__ float g_deg[N_NODES];
__device__ float g_dinv[N_NODES];
__device__ float g_accum[N_NODES * HC];   // Σ exp·xl (unnormalized)
__device__ float g_h[N_NODES * C];        // dinv[n]·elu(head-mean)  (GCN src-prescaled)
__device__ float g_agg[N_NODES * C];

// ---------------- helpers ------------------------------------------------------------------
__device__ __forceinline__ void red_add_v4(float* p, float x, float y, float z, float w) {
    asm volatile("red.global.add.v4.f32 [%0], {%1,%2,%3,%4};"
                 :: "l"(p), "f"(x), "f"(y), "f"(z), "f"(w) : "memory");
}
__device__ __forceinline__ unsigned long long pack2(float lo, float hi) {
    unsigned long long r;
    asm("mov.b64 %0, {%1,%2};" : "=l"(r) : "f"(lo), "f"(hi));
    return r;
}
__device__ __forceinline__ unsigned long long fma2(unsigned long long a,
                                                   unsigned long long b,
                                                   unsigned long long c) {
    unsigned long long d;
    asm("fma.rn.f32x2 %0, %1, %2, %3;" : "=l"(d) : "l"(a), "l"(b), "l"(c));
    return d;
}
__device__ __forceinline__ float hsum2(unsigned long long v) {
    float lo, hi;
    asm("mov.b64 {%0,%1}, %2;" : "=f"(lo), "=f"(hi) : "l"(v));
    return lo + hi;
}

// ---------------- K-1: detect index dtype --------------------------------------------------
__global__ void k_detect(const int* __restrict__ ei32) {
    if (threadIdx.x == 0 && blockIdx.x == 0) {
        int odd_zero = 1;
        for (int i = 1; i < 64; i += 2)
            if (ei32[i] != 0) { odd_zero = 0; break; }
        g_is64 = odd_zero;
    }
}

// ---------------- K-2: normalize indices to int32 ------------------------------------------
__global__ void k_convert(const void* __restrict__ ei) {
    int e = blockIdx.x * blockDim.x + threadIdx.x;
    if (e >= E_EDGES) return;
    if (g_is64) {
        const long long* p = (const long long*)ei;
        g_src[e] = (int)p[e];
        g_dst[e] = (int)p[E_EDGES + e];
    } else {
        const int* p = (const int*)ei;
        g_src[e] = p[e];
        g_dst[e] = p[E_EDGES + e];
    }
}

// ---------------- K0: zero accumulators ----------------------------------------------------
__global__ void k_zero() {
    int i = blockIdx.x * blockDim.x + threadIdx.x;
    int stride = gridDim.x * blockDim.x;
    for (int j = i; j < N_NODES * HC; j += stride) g_accum[j] = 0.0f;
    for (int j = i; j < N_NODES * C;  j += stride) g_agg[j]   = 0.0f;
    for (int j = i; j < N_NODES * NHEAD; j += stride) g_denom[j] = 0.0f;
    for (int j = i; j < N_NODES; j += stride) g_deg[j] = 0.0f;
}

// ---------------- K1: node linear (f32x2 packed FMA) ---------------------------------------
#define NL_TILE 16
__global__ void __launch_bounds__(256, 2) k_node_linear(const float* __restrict__ x,
                                                        const float* __restrict__ Wl,
                                                        const float* __restrict__ Wr) {
    __shared__ float sw[256 * 33];      // padded: conflict-free column reads
    __shared__ float sx[NL_TILE * DIN];
    int o = threadIdx.x;
    unsigned long long wl[DIN / 2], wr[DIN / 2];   // packed over k: no register duplication
    for (int i = threadIdx.x; i < 256 * DIN; i += 256)
        sw[(i >> 5) * 33 + (i & 31)] = Wl[i];
    __syncthreads();
    #pragma unroll
    for (int k = 0; k < DIN / 2; k++) wl[k] = pack2(sw[o * 33 + 2 * k], sw[o * 33 + 2 * k + 1]);
    __syncthreads();
    for (int i = threadIdx.x; i < 256 * DIN; i += 256)
        sw[(i >> 5) * 33 + (i & 31)] = Wr[i];
    __syncthreads();
    #pragma unroll
    for (int k = 0; k < DIN / 2; k++) wr[k] = pack2(sw[o * 33 + 2 * k], sw[o * 33 + 2 * k + 1]);

    for (int base = blockIdx.x * NL_TILE; base < N_NODES; base += gridDim.x * NL_TILE) {
        int nn = min(NL_TILE, N_NODES - base);
        __syncthreads();
        for (int i = threadIdx.x; i < nn * DIN; i += 256)
            sx[i] = x[base * DIN + i];
        __syncthreads();
        for (int j = 0; j < nn; j++) {
            const unsigned long long* sxp = (const unsigned long long*)(sx + j * DIN);
            unsigned long long al2 = 0, ar2 = 0;   // 0 == packed {0.f,0.f}
            #pragma unroll
            for (int k = 0; k < DIN / 2; k++) {
                unsigned long long xv = sxp[k];    // LDS.64 broadcast
                al2 = fma2(wl[k], xv, al2);
                ar2 = fma2(wr[k], xv, ar2);
            }
            g_xl[(size_t)(base + j) * HC + o] = hsum2(al2);
            g_xr[(size_t)(base + j) * HC + o] = hsum2(ar2);
        }
    }
}

// ---------------- K2: FUSED edge attention + aggregation -----------------------------------
// warp per edge; lane l: channels [4l,4l+4) (head l>>4) and [128+4l,...) (head 2+(l>>4)).
// Softmax normalization deferred to k_elu_mean -> single pass over edges.
__global__ void k_edge_fused(const float* __restrict__ att) {
    __shared__ float satt[HC];
    if (threadIdx.x < HC) satt[threadIdx.x] = att[threadIdx.x];
    __syncthreads();
    int e = blockIdx.x * (blockDim.x >> 5) + (threadIdx.x >> 5);
    if (e >= E_EDGES) return;
    int l = threadIdx.x & 31;
    int src = g_src[e];
    int dst = g_dst[e];
    const float4* pl = (const float4*)(g_xl + (size_t)src * HC);
    const float4* pr = (const float4*)(g_xr + (size_t)dst * HC);
    float4 a0 = pl[l],      b0 = pr[l];
    float4 a1 = pl[32 + l], b1 = pr[32 + l];
    float p0 = 0.0f, p1 = 0.0f, v;
    v = a0.x + b0.x; v = v > 0.0f ? v : 0.2f * v; p0 += v * satt[4*l+0];
    v = a0.y + b0.y; v = v > 0.0f ? v : 0.2f * v; p0 += v * satt[4*l+1];
    v = a0.z + b0.z; v = v > 0.0f ? v : 0.2f * v; p0 += v * satt[4*l+2];
    v = a0.w + b0.w; v = v > 0.0f ? v : 0.2f * v; p0 += v * satt[4*l+3];
    v = a1.x + b1.x; v = v > 0.0f ? v : 0.2f * v; p1 += v * satt[128+4*l+0];
    v = a1.y + b1.y; v = v > 0.0f ? v : 0.2f * v; p1 += v * satt[128+4*l+1];
    v = a1.z + b1.z; v = v > 0.0f ? v : 0.2f * v; p1 += v * satt[128+4*l+2];
    v = a1.w + b1.w; v = v > 0.0f ? v : 0.2f * v; p1 += v * satt[128+4*l+3];
    #pragma unroll
    for (int s = 8; s >= 1; s >>= 1) {   // xor-reduce: all 16 lanes get the group sum
        p0 += __shfl_xor_sync(0xffffffffu, p0, s);
        p1 += __shfl_xor_sync(0xffffffffu, p1, s);
    }
    float ex0 = __expf(p0);   // unnormalized attention weight (no-max softmax, fp32-safe)
    float ex1 = __expf(p1);
    float* dp = g_accum + (size_t)dst * HC;
    red_add_v4(dp + 4 * l,       a0.x * ex0, a0.y * ex0, a0.z * ex0, a0.w * ex0);
    red_add_v4(dp + 128 + 4 * l, a1.x * ex1, a1.y * ex1, a1.z * ex1, a1.w * ex1);
    if ((l & 15) == 0) {
        int h = l >> 4;
        atomicAdd(&g_denom[dst * NHEAD + h],     ex0);
        atomicAdd(&g_denom[dst * NHEAD + 2 + h], ex1);
    }
    if (l == 0) atomicAdd(&g_deg[dst], 1.0f);
}

// ---------------- K5: degree -> rsqrt ------------------------------------------------------
__global__ void k_dinv() {
    int n = blockIdx.x * blockDim.x + threadIdx.x;
    if (n < N_NODES) {
        float d = g_deg[n];
        g_dinv[n] = d > 0.0f ? rsqrtf(d) : 0.0f;
    }
}

// ---------------- K4: per-node softmax divide + head-mean + ELU + GCN src prescale ---------
__global__ void k_elu_mean() {
    int i = blockIdx.x * blockDim.x + threadIdx.x;
    if (i >= N_NODES * C) return;
    int n = i >> 6, c = i & 63;
    const float* a = g_accum + (size_t)n * HC;
    const float* d = g_denom + n * NHEAD;
    float m = 0.25f * (a[c]           / (d[0] + 1e-16f)
                     + a[C + c]       / (d[1] + 1e-16f)
                     + a[2 * C + c]   / (d[2] + 1e-16f)
                     + a[3 * C + c]   / (d[3] + 1e-16f));
    float h = m > 0.0f ? m : expm1f(m);
    g_h[i] = h * g_dinv[n];            // fold dinv[src] into the message
}

// ---------------- K6: GCN aggregation: bare gather + vec4 RED ------------------------------
__global__ void k_edge_gcn() {
    int warp = blockIdx.x * (blockDim.x >> 5) + (threadIdx.x >> 5);
    int l = threadIdx.x & 31;
    int e = warp * 2 + (l >> 4);
    if (e >= E_EDGES) return;
    int c4 = l & 15;
    int src = g_src[e];
    int dst = g_dst[e];
    float4 v = ((const float4*)(g_h + (size_t)src * C))[c4];
    red_add_v4(g_agg + (size_t)dst * C + 4 * c4, v.x, v.y, v.z, v.w);
}

// ---------------- K7: final linear (f32x2), dinv[dst] folded into tile load ----------------
#define OL_TILE 8
__global__ void __launch_bounds__(128) k_out_linear(const float* __restrict__ Wg,
                                                    float* __restrict__ out) {
    __shared__ float sw[DOUT * 65];
    __shared__ float sh[OL_TILE * C];
    int o = threadIdx.x;
    unsigned long long wg[C / 2];
    for (int i = threadIdx.x; i < DOUT * C; i += 128)
        sw[(i >> 6) * 65 + (i & 63)] = Wg[i];
    __syncthreads();
    #pragma unroll
    for (int k = 0; k < C / 2; k++) wg[k] = pack2(sw[o * 65 + 2 * k], sw[o * 65 + 2 * k + 1]);

    for (int base = blockIdx.x * OL_TILE; base < N_NODES; base += gridDim.x * OL_TILE) {
        int nn = min(OL_TILE, N_NODES - base);
        __syncthreads();
        for (int i = threadIdx.x; i < nn * C; i += 128)
            sh[i] = g_agg[(size_t)base * C + i] * g_dinv[base + (i >> 6)];
        __syncthreads();
        for (int j = 0; j < nn; j++) {
            const unsigned long long* shp = (const unsigned long long*)(sh + j * C);
            unsigned long long s2 = 0;
            #pragma unroll
            for (int k = 0; k < C / 2; k++)
                s2 = fma2(wg[k], shp[k], s2);
            out[(size_t)(base + j) * DOUT + o] = hsum2(s2);
        }
    }
}

// ---------------- launch -------------------------------------------------------------------
extern "C" void kernel_launch(void* const* d_in, const int* in_sizes, int n_in,
                              void* d_out, int out_size) {
    const float* x   = (const float*)d_in[0];
    const void*  ei  = d_in[1];
    const float* Wl  = (const float*)d_in[2];
    const float* Wr  = (const float*)d_in[3];
    const float* att = (const float*)d_in[4];
    const float* Wg  = (const float*)d_in[5];
    float* out = (float*)d_out;
    (void)in_sizes; (void)n_in; (void)out_size;

    const int EDGE_BLOCKS  = (E_EDGES + 7) / 8;    // warp-per-edge
    const int EDGE_BLOCKS2 = (E_EDGES + 15) / 16;  // 2 edges/warp

    k_detect<<<1, 32>>>((const int*)ei);
    k_convert<<<(E_EDGES + 255) / 256, 256>>>(ei);
    k_zero<<<1184, 256>>>();
    k_node_linear<<<1184, 256>>>(x, Wl, Wr);
    k_edge_fused<<<EDGE_BLOCKS, 256>>>(att);
    k_dinv<<<(N_NODES + 255) / 256, 256>>>();
    k_elu_mean<<<(N_NODES * C + 255) / 256, 256>>>();
    k_edge_gcn<<<EDGE_BLOCKS2, 256>>>();
    k_out_linear<<<592, 128>>>(Wg, out);
}

// round 7
// speedup vs baseline: 6.1915x; 1.2560x over previous
#include <cuda_runtime.h>
#include <cuda_bf16.h>
#include <cstdint>

#define N_NODES 50000
#define E_EDGES 800000
#define NHEAD 4
#define C 64
#define DIN 32
#define DOUT 128
#define HC 256   // NHEAD * C

// ---------------- device scratch ----------------------------------------------------------
__device__ int   g_is64;
__device__ int   g_src[E_EDGES];
__device__ int   g_dst[E_EDGES];
__device__ int   g_cnt[N_NODES];         // in-degree histogram
__device__ int   g_rowptr[N_NODES + 1];  // CSR row pointers (by dst)
__device__ int   g_cursor[N_NODES];      // fill cursors
__device__ int   g_csrc[E_EDGES];        // src node per CSR slot
__device__ float g_xl[N_NODES * HC];
__device__ float g_xr[N_NODES * HC];
__device__ float g_h[N_NODES * C];       // dinv[n]*elu(head-mean)
__device__ float g_agg[N_NODES * C];

// ---------------- helpers ------------------------------------------------------------------
__device__ __forceinline__ unsigned long long pack2(float lo, float hi) {
    unsigned long long r;
    asm("mov.b64 %0, {%1,%2};" : "=l"(r) : "f"(lo), "f"(hi));
    return r;
}
__device__ __forceinline__ unsigned long long fma2(unsigned long long a,
                                                   unsigned long long b,
                                                   unsigned long long c) {
    unsigned long long d;
    asm("fma.rn.f32x2 %0, %1, %2, %3;" : "=l"(d) : "l"(a), "l"(b), "l"(c));
    return d;
}
__device__ __forceinline__ float hsum2(unsigned long long v) {
    float lo, hi;
    asm("mov.b64 {%0,%1}, %2;" : "=f"(lo), "=f"(hi) : "l"(v));
    return lo + hi;
}

// ---------------- K0: zero histogram -------------------------------------------------------
__global__ void k_zero_cnt() {
    int i = blockIdx.x * blockDim.x + threadIdx.x;
    if (i < N_NODES) g_cnt[i] = 0;
}

// ---------------- K1: detect index dtype ---------------------------------------------------
__global__ void k_detect(const int* __restrict__ ei32) {
    if (threadIdx.x == 0 && blockIdx.x == 0) {
        int odd_zero = 1;
        for (int i = 1; i < 64; i += 2)
            if (ei32[i] != 0) { odd_zero = 0; break; }
        g_is64 = odd_zero;
    }
}

// ---------------- K2: convert indices + degree histogram -----------------------------------
__global__ void k_convert_hist(const void* __restrict__ ei) {
    int e = blockIdx.x * blockDim.x + threadIdx.x;
    if (e >= E_EDGES) return;
    int s, d;
    if (g_is64) {
        const long long* p = (const long long*)ei;
        s = (int)p[e];
        d = (int)p[E_EDGES + e];
    } else {
        const int* p = (const int*)ei;
        s = p[e];
        d = p[E_EDGES + e];
    }
    g_src[e] = s;
    g_dst[e] = d;
    atomicAdd(&g_cnt[d], 1);
}

// ---------------- K3: exclusive scan (single block, deterministic) -------------------------
#define SCAN_T 1024
#define SCAN_CHUNK ((N_NODES + SCAN_T - 1) / SCAN_T)
__global__ void __launch_bounds__(SCAN_T) k_scan() {
    __shared__ int part[SCAN_T];
    int t = threadIdx.x;
    int s0 = t * SCAN_CHUNK;
    int s1 = min(s0 + SCAN_CHUNK, N_NODES);
    int s = 0;
    for (int i = s0; i < s1; i++) s += g_cnt[i];
    part[t] = s;
    __syncthreads();
    for (int off = 1; off < SCAN_T; off <<= 1) {   // Hillis-Steele inclusive
        int v = (t >= off) ? part[t - off] : 0;
        __syncthreads();
        part[t] += v;
        __syncthreads();
    }
    int pre = (t == 0) ? 0 : part[t - 1];          // exclusive prefix for this chunk
    for (int i = s0; i < s1; i++) {
        g_rowptr[i] = pre;
        g_cursor[i] = pre;
        pre += g_cnt[i];
    }
    if (t == SCAN_T - 1) g_rowptr[N_NODES] = part[SCAN_T - 1];
}

// ---------------- K4: CSR fill -------------------------------------------------------------
__global__ void k_fill() {
    int e = blockIdx.x * blockDim.x + threadIdx.x;
    if (e >= E_EDGES) return;
    int pos = atomicAdd(&g_cursor[g_dst[e]], 1);
    g_csrc[pos] = g_src[e];
}

// ---------------- K5: node linear (f32x2 packed FMA) ---------------------------------------
#define NL_TILE 16
__global__ void __launch_bounds__(256, 2) k_node_linear(const float* __restrict__ x,
                                                        const float* __restrict__ Wl,
                                                        const float* __restrict__ Wr) {
    __shared__ float sw[256 * 33];
    __shared__ float sx[NL_TILE * DIN];
    int o = threadIdx.x;
    unsigned long long wl[DIN / 2], wr[DIN / 2];
    for (int i = threadIdx.x; i < 256 * DIN; i += 256)
        sw[(i >> 5) * 33 + (i & 31)] = Wl[i];
    __syncthreads();
    #pragma unroll
    for (int k = 0; k < DIN / 2; k++) wl[k] = pack2(sw[o * 33 + 2 * k], sw[o * 33 + 2 * k + 1]);
    __syncthreads();
    for (int i = threadIdx.x; i < 256 * DIN; i += 256)
        sw[(i >> 5) * 33 + (i & 31)] = Wr[i];
    __syncthreads();
    #pragma unroll
    for (int k = 0; k < DIN / 2; k++) wr[k] = pack2(sw[o * 33 + 2 * k], sw[o * 33 + 2 * k + 1]);

    for (int base = blockIdx.x * NL_TILE; base < N_NODES; base += gridDim.x * NL_TILE) {
        int nn = min(NL_TILE, N_NODES - base);
        __syncthreads();
        for (int i = threadIdx.x; i < nn * DIN; i += 256)
            sx[i] = x[base * DIN + i];
        __syncthreads();
        for (int j = 0; j < nn; j++) {
            const unsigned long long* sxp = (const unsigned long long*)(sx + j * DIN);
            unsigned long long al2 = 0, ar2 = 0;
            #pragma unroll
            for (int k = 0; k < DIN / 2; k++) {
                unsigned long long xv = sxp[k];
                al2 = fma2(wl[k], xv, al2);
                ar2 = fma2(wr[k], xv, ar2);
            }
            g_xl[(size_t)(base + j) * HC + o] = hsum2(al2);
            g_xr[(size_t)(base + j) * HC + o] = hsum2(ar2);
        }
    }
}

// ---------------- K6: node-centric fused GAT (no atomics) ----------------------------------
// Warp per dst node. Lane l: float4 at idx l (head l>>4, ch 4*(l&15)..) and idx 32+l
// (head 2+(l>>4)). xr loaded once per node; per-edge: gather xl, logit, exp, reg-accumulate.
// Epilogue: softmax divide, head-mean (xor-16 shuffle), ELU, dinv prescale -> g_h.
__global__ void __launch_bounds__(256) k_gat_node(const float* __restrict__ att) {
    __shared__ float satt[HC];
    if (threadIdx.x < HC) satt[threadIdx.x] = att[threadIdx.x];
    __syncthreads();
    int n = blockIdx.x * 8 + (threadIdx.x >> 5);
    if (n >= N_NODES) return;
    int l = threadIdx.x & 31;
    int beg = g_rowptr[n], end = g_rowptr[n + 1];

    const float4* pr = (const float4*)(g_xr + (size_t)n * HC);
    float4 b0 = pr[l], b1 = pr[32 + l];
    float t0x = satt[4*l+0], t0y = satt[4*l+1], t0z = satt[4*l+2], t0w = satt[4*l+3];
    float t1x = satt[128+4*l+0], t1y = satt[128+4*l+1], t1z = satt[128+4*l+2], t1w = satt[128+4*l+3];

    float4 acc0 = {0.f,0.f,0.f,0.f}, acc1 = {0.f,0.f,0.f,0.f};
    float den0 = 0.f, den1 = 0.f;

    for (int i = beg; i < end; i++) {
        int src = __ldg(&g_csrc[i]);
        const float4* pl = (const float4*)(g_xl + (size_t)src * HC);
        float4 a0 = pl[l], a1 = pl[32 + l];
        float p0 = 0.f, p1 = 0.f, v;
        v = a0.x + b0.x; v = v > 0.f ? v : 0.2f * v; p0 += v * t0x;
        v = a0.y + b0.y; v = v > 0.f ? v : 0.2f * v; p0 += v * t0y;
        v = a0.z + b0.z; v = v > 0.f ? v : 0.2f * v; p0 += v * t0z;
        v = a0.w + b0.w; v = v > 0.f ? v : 0.2f * v; p0 += v * t0w;
        v = a1.x + b1.x; v = v > 0.f ? v : 0.2f * v; p1 += v * t1x;
        v = a1.y + b1.y; v = v > 0.f ? v : 0.2f * v; p1 += v * t1y;
        v = a1.z + b1.z; v = v > 0.f ? v : 0.2f * v; p1 += v * t1z;
        v = a1.w + b1.w; v = v > 0.f ? v : 0.2f * v; p1 += v * t1w;
        #pragma unroll
        for (int s = 8; s >= 1; s >>= 1) {   // 16-lane group sums
            p0 += __shfl_xor_sync(0xffffffffu, p0, s);
            p1 += __shfl_xor_sync(0xffffffffu, p1, s);
        }
        float ex0 = __expf(p0);
        float ex1 = __expf(p1);
        acc0.x += a0.x * ex0; acc0.y += a0.y * ex0; acc0.z += a0.z * ex0; acc0.w += a0.w * ex0;
        acc1.x += a1.x * ex1; acc1.y += a1.y * ex1; acc1.z += a1.z * ex1; acc1.w += a1.w * ex1;
        den0 += ex0; den1 += ex1;
    }

    float inv0 = 1.0f / (den0 + 1e-16f);
    float inv1 = 1.0f / (den1 + 1e-16f);
    float sx = acc0.x * inv0 + acc1.x * inv1;   // this lane's two heads, channel 4*(l&15)+0
    float sy = acc0.y * inv0 + acc1.y * inv1;
    float sz = acc0.z * inv0 + acc1.z * inv1;
    float sw = acc0.w * inv0 + acc1.w * inv1;
    sx += __shfl_xor_sync(0xffffffffu, sx, 16); // + other lane-half's two heads
    sy += __shfl_xor_sync(0xffffffffu, sy, 16);
    sz += __shfl_xor_sync(0xffffffffu, sz, 16);
    sw += __shfl_xor_sync(0xffffffffu, sw, 16);
    if (l < 16) {
        float deg = (float)(end - beg);
        float dinv = deg > 0.f ? rsqrtf(deg) : 0.f;
        float4 o;
        float m;
        m = 0.25f * sx; m = m > 0.f ? m : expm1f(m); o.x = m * dinv;
        m = 0.25f * sy; m = m > 0.f ? m : expm1f(m); o.y = m * dinv;
        m = 0.25f * sz; m = m > 0.f ? m : expm1f(m); o.z = m * dinv;
        m = 0.25f * sw; m = m > 0.f ? m : expm1f(m); o.w = m * dinv;
        ((float4*)(g_h + (size_t)n * C))[l] = o;
    }
}

// ---------------- K7: node-centric GCN aggregate (no atomics) ------------------------------
// Warp per dst node; lane l owns float2 (channels 2l,2l+1). dinv[dst] applied in epilogue.
__global__ void __launch_bounds__(256) k_gcn_node() {
    int n = blockIdx.x * 8 + (threadIdx.x >> 5);
    if (n >= N_NODES) return;
    int l = threadIdx.x & 31;
    int beg = g_rowptr[n], end = g_rowptr[n + 1];
    float ax = 0.f, ay = 0.f;
    for (int i = beg; i < end; i++) {
        int src = __ldg(&g_csrc[i]);
        float2 v = ((const float2*)(g_h + (size_t)src * C))[l];
        ax += v.x; ay += v.y;
    }
    float deg = (float)(end - beg);
    float dinv = deg > 0.f ? rsqrtf(deg) : 0.f;
    float2 o; o.x = ax * dinv; o.y = ay * dinv;
    ((float2*)(g_agg + (size_t)n * C))[l] = o;
}

// ---------------- K8: final linear (f32x2) -------------------------------------------------
#define OL_TILE 8
__global__ void __launch_bounds__(128) k_out_linear(const float* __restrict__ Wg,
                                                    float* __restrict__ out) {
    __shared__ float sw[DOUT * 65];
    __shared__ float sh[OL_TILE * C];
    int o = threadIdx.x;
    unsigned long long wg[C / 2];
    for (int i = threadIdx.x; i < DOUT * C; i += 128)
        sw[(i >> 6) * 65 + (i & 63)] = Wg[i];
    __syncthreads();
    #pragma unroll
    for (int k = 0; k < C / 2; k++) wg[k] = pack2(sw[o * 65 + 2 * k], sw[o * 65 + 2 * k + 1]);

    for (int base = blockIdx.x * OL_TILE; base < N_NODES; base += gridDim.x * OL_TILE) {
        int nn = min(OL_TILE, N_NODES - base);
        __syncthreads();
        for (int i = threadIdx.x; i < nn * C; i += 128)
            sh[i] = g_agg[(size_t)base * C + i];
        __syncthreads();
        for (int j = 0; j < nn; j++) {
            const unsigned long long* shp = (const unsigned long long*)(sh + j * C);
            unsigned long long s2 = 0;
            #pragma unroll
            for (int k = 0; k < C / 2; k++)
                s2 = fma2(wg[k], shp[k], s2);
            out[(size_t)(base + j) * DOUT + o] = hsum2(s2);
        }
    }
}

// ---------------- launch -------------------------------------------------------------------
extern "C" void kernel_launch(void* const* d_in, const int* in_sizes, int n_in,
                              void* d_out, int out_size) {
    const float* x   = (const float*)d_in[0];
    const void*  ei  = d_in[1];
    const float* Wl  = (const float*)d_in[2];
    const float* Wr  = (const float*)d_in[3];
    const float* att = (const float*)d_in[4];
    const float* Wg  = (const float*)d_in[5];
    float* out = (float*)d_out;
    (void)in_sizes; (void)n_in; (void)out_size;

    k_zero_cnt<<<(N_NODES + 255) / 256, 256>>>();
    k_detect<<<1, 32>>>((const int*)ei);
    k_convert_hist<<<(E_EDGES + 255) / 256, 256>>>(ei);
    k_scan<<<1, SCAN_T>>>();
    k_fill<<<(E_EDGES + 255) / 256, 256>>>();
    k_node_linear<<<1184, 256>>>(x, Wl, Wr);
    k_gat_node<<<(N_NODES + 7) / 8, 256>>>(att);
    k_gcn_node<<<(N_NODES + 7) / 8, 256>>>();
    k_out_linear<<<592, 128>>>(Wg, out);
}

// round 9
// speedup vs baseline: 7.6511x; 1.2357x over previous
#include <cuda_runtime.h>
#include <cuda_bf16.h>
#include <cstdint>

#define N_NODES 50000
#define E_EDGES 800000
#define NHEAD 4
#define C 64
#define DIN 32
#define DOUT 128
#define HC 256   // NHEAD * C

#define CHUNK 16
#define NCHUNK ((N_NODES + CHUNK - 1) / CHUNK)   // 3125

// ---------------- device scratch ----------------------------------------------------------
__device__ int   g_is64;
__device__ int   g_src[E_EDGES];
__device__ int   g_dst[E_EDGES];
__device__ int   g_cnt[N_NODES];         // in-degree histogram
__device__ int   g_chunkpre[NCHUNK];     // exclusive prefix per chunk
__device__ int   g_rowptr[N_NODES + 1];  // CSR row pointers (by dst)
__device__ int   g_cursor[N_NODES];      // fill cursors
__device__ int   g_csrc[E_EDGES];        // src node per CSR slot
__device__ float g_xl[N_NODES * HC];
__device__ float g_xr[N_NODES * HC];
__device__ float g_h[N_NODES * C];       // dinv[n]*elu(head-mean)
__device__ float g_agg[N_NODES * C];

// ---------------- helpers ------------------------------------------------------------------
__device__ __forceinline__ unsigned long long pack2(float lo, float hi) {
    unsigned long long r;
    asm("mov.b64 %0, {%1,%2};" : "=l"(r) : "f"(lo), "f"(hi));
    return r;
}
__device__ __forceinline__ unsigned long long fma2(unsigned long long a,
                                                   unsigned long long b,
                                                   unsigned long long c) {
    unsigned long long d;
    asm("fma.rn.f32x2 %0, %1, %2, %3;" : "=l"(d) : "l"(a), "l"(b), "l"(c));
    return d;
}
__device__ __forceinline__ float hsum2(unsigned long long v) {
    float lo, hi;
    asm("mov.b64 {%0,%1}, %2;" : "=f"(lo), "=f"(hi) : "l"(v));
    return lo + hi;
}

// ---------------- K0: zero histogram -------------------------------------------------------
__global__ void k_zero_cnt() {
    int i = blockIdx.x * blockDim.x + threadIdx.x;
    if (i < N_NODES) g_cnt[i] = 0;
}

// ---------------- K1: detect index dtype ---------------------------------------------------
__global__ void k_detect(const int* __restrict__ ei32) {
    if (threadIdx.x == 0 && blockIdx.x == 0) {
        int odd_zero = 1;
        for (int i = 1; i < 64; i += 2)
            if (ei32[i] != 0) { odd_zero = 0; break; }
        g_is64 = odd_zero;
    }
}

// ---------------- K2: convert indices + degree histogram -----------------------------------
__global__ void k_convert_hist(const void* __restrict__ ei) {
    int e = blockIdx.x * blockDim.x + threadIdx.x;
    if (e >= E_EDGES) return;
    int s, d;
    if (g_is64) {
        const long long* p = (const long long*)ei;
        s = (int)p[e];
        d = (int)p[E_EDGES + e];
    } else {
        const int* p = (const int*)ei;
        s = p[e];
        d = p[E_EDGES + e];
    }
    g_src[e] = s;
    g_dst[e] = d;
    atomicAdd(&g_cnt[d], 1);
}

// ---------------- K3a: per-chunk sums (grid-parallel) --------------------------------------
__device__ int g_chunksum[NCHUNK];
__global__ void k_chunk_sum() {
    int c = blockIdx.x * blockDim.x + threadIdx.x;
    if (c >= NCHUNK) return;
    int b = c * CHUNK;
    int e = min(b + CHUNK, N_NODES);
    int s = 0;
    #pragma unroll 4
    for (int i = b; i < e; i++) s += g_cnt[i];
    g_chunksum[c] = s;
}

// ---------------- K3b: scan 3125 chunk sums in one block -----------------------------------
#define SCAN_T 1024
#define PER_T  ((NCHUNK + SCAN_T - 1) / SCAN_T)   // 4
__global__ void __launch_bounds__(SCAN_T) k_scan_chunks() {
    __shared__ int part[SCAN_T];
    int t = threadIdx.x;
    int v[PER_T];
    int s = 0;
    #pragma unroll
    for (int j = 0; j < PER_T; j++) {
        int c = t * PER_T + j;
        v[j] = (c < NCHUNK) ? g_chunksum[c] : 0;
        s += v[j];
    }
    part[t] = s;
    __syncthreads();
    for (int off = 1; off < SCAN_T; off <<= 1) {
        int u = (t >= off) ? part[t - off] : 0;
        __syncthreads();
        part[t] += u;
        __syncthreads();
    }
    int pre = (t == 0) ? 0 : part[t - 1];
    #pragma unroll
    for (int j = 0; j < PER_T; j++) {
        int c = t * PER_T + j;
        if (c < NCHUNK) g_chunkpre[c] = pre;
        pre += v[j];
    }
    if (t == SCAN_T - 1) g_rowptr[N_NODES] = part[SCAN_T - 1];
}

// ---------------- K3c: expand rowptr/cursor (grid-parallel) --------------------------------
__global__ void k_fill_rowptr() {
    int c = blockIdx.x * blockDim.x + threadIdx.x;
    if (c >= NCHUNK) return;
    int b = c * CHUNK;
    int e = min(b + CHUNK, N_NODES);
    int pre = g_chunkpre[c];
    for (int i = b; i < e; i++) {
        g_rowptr[i] = pre;
        g_cursor[i] = pre;
        pre += g_cnt[i];
    }
}

// ---------------- K4: CSR fill -------------------------------------------------------------
__global__ void k_fill() {
    int e = blockIdx.x * blockDim.x + threadIdx.x;
    if (e >= E_EDGES) return;
    int pos = atomicAdd(&g_cursor[g_dst[e]], 1);
    g_csrc[pos] = g_src[e];
}

// ---------------- K5: node linear (f32x2 packed FMA) ---------------------------------------
#define NL_TILE 16
__global__ void __launch_bounds__(256, 2) k_node_linear(const float* __restrict__ x,
                                                        const float* __restrict__ Wl,
                                                        const float* __restrict__ Wr) {
    __shared__ float sw[256 * 33];
    __shared__ float sx[NL_TILE * DIN];
    int o = threadIdx.x;
    unsigned long long wl[DIN / 2], wr[DIN / 2];
    for (int i = threadIdx.x; i < 256 * DIN; i += 256)
        sw[(i >> 5) * 33 + (i & 31)] = Wl[i];
    __syncthreads();
    #pragma unroll
    for (int k = 0; k < DIN / 2; k++) wl[k] = pack2(sw[o * 33 + 2 * k], sw[o * 33 + 2 * k + 1]);
    __syncthreads();
    for (int i = threadIdx.x; i < 256 * DIN; i += 256)
        sw[(i >> 5) * 33 + (i & 31)] = Wr[i];
    __syncthreads();
    #pragma unroll
    for (int k = 0; k < DIN / 2; k++) wr[k] = pack2(sw[o * 33 + 2 * k], sw[o * 33 + 2 * k + 1]);

    for (int base = blockIdx.x * NL_TILE; base < N_NODES; base += gridDim.x * NL_TILE) {
        int nn = min(NL_TILE, N_NODES - base);
        __syncthreads();
        for (int i = threadIdx.x; i < nn * DIN; i += 256)
            sx[i] = x[base * DIN + i];
        __syncthreads();
        for (int j = 0; j < nn; j++) {
            const unsigned long long* sxp = (const unsigned long long*)(sx + j * DIN);
            unsigned long long al2 = 0, ar2 = 0;
            #pragma unroll
            for (int k = 0; k < DIN / 2; k++) {
                unsigned long long xv = sxp[k];
                al2 = fma2(wl[k], xv, al2);
                ar2 = fma2(wr[k], xv, ar2);
            }
            g_xl[(size_t)(base + j) * HC + o] = hsum2(al2);
            g_xr[(size_t)(base + j) * HC + o] = hsum2(ar2);
        }
    }
}

// ---------------- K6: node-centric fused GAT (no atomics) ----------------------------------
__global__ void __launch_bounds__(256) k_gat_node(const float* __restrict__ att) {
    __shared__ float satt[HC];
    if (threadIdx.x < HC) satt[threadIdx.x] = att[threadIdx.x];
    __syncthreads();
    int n = blockIdx.x * 8 + (threadIdx.x >> 5);
    if (n >= N_NODES) return;
    int l = threadIdx.x & 31;
    int beg = g_rowptr[n], end = g_rowptr[n + 1];

    const float4* pr = (const float4*)(g_xr + (size_t)n * HC);
    float4 b0 = pr[l], b1 = pr[32 + l];
    float t0x = satt[4*l+0], t0y = satt[4*l+1], t0z = satt[4*l+2], t0w = satt[4*l+3];
    float t1x = satt[128+4*l+0], t1y = satt[128+4*l+1], t1z = satt[128+4*l+2], t1w = satt[128+4*l+3];

    float4 acc0 = {0.f,0.f,0.f,0.f}, acc1 = {0.f,0.f,0.f,0.f};
    float den0 = 0.f, den1 = 0.f;

    for (int i = beg; i < end; i++) {
        int src = __ldg(&g_csrc[i]);
        const float4* pl = (const float4*)(g_xl + (size_t)src * HC);
        float4 a0 = pl[l], a1 = pl[32 + l];
        float p0 = 0.f, p1 = 0.f, v;
        v = a0.x + b0.x; v = v > 0.f ? v : 0.2f * v; p0 += v * t0x;
        v = a0.y + b0.y; v = v > 0.f ? v : 0.2f * v; p0 += v * t0y;
        v = a0.z + b0.z; v = v > 0.f ? v : 0.2f * v; p0 += v * t0z;
        v = a0.w + b0.w; v = v > 0.f ? v : 0.2f * v; p0 += v * t0w;
        v = a1.x + b1.x; v = v > 0.f ? v : 0.2f * v; p1 += v * t1x;
        v = a1.y + b1.y; v = v > 0.f ? v : 0.2f * v; p1 += v * t1y;
        v = a1.z + b1.z; v = v > 0.f ? v : 0.2f * v; p1 += v * t1z;
        v = a1.w + b1.w; v = v > 0.f ? v : 0.2f * v; p1 += v * t1w;
        #pragma unroll
        for (int s = 8; s >= 1; s >>= 1) {
            p0 += __shfl_xor_sync(0xffffffffu, p0, s);
            p1 += __shfl_xor_sync(0xffffffffu, p1, s);
        }
        float ex0 = __expf(p0);
        float ex1 = __expf(p1);
        acc0.x += a0.x * ex0; acc0.y += a0.y * ex0; acc0.z += a0.z * ex0; acc0.w += a0.w * ex0;
        acc1.x += a1.x * ex1; acc1.y += a1.y * ex1; acc1.z += a1.z * ex1; acc1.w += a1.w * ex1;
        den0 += ex0; den1 += ex1;
    }

    float inv0 = 1.0f / (den0 + 1e-16f);
    float inv1 = 1.0f / (den1 + 1e-16f);
    float sx = acc0.x * inv0 + acc1.x * inv1;
    float sy = acc0.y * inv0 + acc1.y * inv1;
    float sz = acc0.z * inv0 + acc1.z * inv1;
    float sw = acc0.w * inv0 + acc1.w * inv1;
    sx += __shfl_xor_sync(0xffffffffu, sx, 16);
    sy += __shfl_xor_sync(0xffffffffu, sy, 16);
    sz += __shfl_xor_sync(0xffffffffu, sz, 16);
    sw += __shfl_xor_sync(0xffffffffu, sw, 16);
    if (l < 16) {
        float deg = (float)(end - beg);
        float dinv = deg > 0.f ? rsqrtf(deg) : 0.f;
        float4 o;
        float m;
        m = 0.25f * sx; m = m > 0.f ? m : expm1f(m); o.x = m * dinv;
        m = 0.25f * sy; m = m > 0.f ? m : expm1f(m); o.y = m * dinv;
        m = 0.25f * sz; m = m > 0.f ? m : expm1f(m); o.z = m * dinv;
        m = 0.25f * sw; m = m > 0.f ? m : expm1f(m); o.w = m * dinv;
        ((float4*)(g_h + (size_t)n * C))[l] = o;
    }
}

// ---------------- K7: node-centric GCN aggregate (no atomics) ------------------------------
__global__ void __launch_bounds__(256) k_gcn_node() {
    int n = blockIdx.x * 8 + (threadIdx.x >> 5);
    if (n >= N_NODES) return;
    int l = threadIdx.x & 31;
    int beg = g_rowptr[n], end = g_rowptr[n + 1];
    float ax = 0.f, ay = 0.f;
    for (int i = beg; i < end; i++) {
        int src = __ldg(&g_csrc[i]);
        float2 v = ((const float2*)(g_h + (size_t)src * C))[l];
        ax += v.x; ay += v.y;
    }
    float deg = (float)(end - beg);
    float dinv = deg > 0.f ? rsqrtf(deg) : 0.f;
    float2 o; o.x = ax * dinv; o.y = ay * dinv;
    ((float2*)(g_agg + (size_t)n * C))[l] = o;
}

// ---------------- K8: final linear (f32x2) -------------------------------------------------
#define OL_TILE 8
__global__ void __launch_bounds__(128) k_out_linear(const float* __restrict__ Wg,
                                                    float* __restrict__ out) {
    __shared__ float sw[DOUT * 65];
    __shared__ float sh[OL_TILE * C];
    int o = threadIdx.x;
    unsigned long long wg[C / 2];
    for (int i = threadIdx.x; i < DOUT * C; i += 128)
        sw[(i >> 6) * 65 + (i & 63)] = Wg[i];
    __syncthreads();
    #pragma unroll
    for (int k = 0; k < C / 2; k++) wg[k] = pack2(sw[o * 65 + 2 * k], sw[o * 65 + 2 * k + 1]);

    for (int base = blockIdx.x * OL_TILE; base < N_NODES; base += gridDim.x * OL_TILE) {
        int nn = min(OL_TILE, N_NODES - base);
        __syncthreads();
        for (int i = threadIdx.x; i < nn * C; i += 128)
            sh[i] = g_agg[(size_t)base * C + i];
        __syncthreads();
        for (int j = 0; j < nn; j++) {
            const unsigned long long* shp = (const unsigned long long*)(sh + j * C);
            unsigned long long s2 = 0;
            #pragma unroll
            for (int k = 0; k < C / 2; k++)
                s2 = fma2(wg[k], shp[k], s2);
            out[(size_t)(base + j) * DOUT + o] = hsum2(s2);
        }
    }
}

// ---------------- launch -------------------------------------------------------------------
extern "C" void kernel_launch(void* const* d_in, const int* in_sizes, int n_in,
                              void* d_out, int out_size) {
    const float* x   = (const float*)d_in[0];
    const void*  ei  = d_in[1];
    const float* Wl  = (const float*)d_in[2];
    const float* Wr  = (const float*)d_in[3];
    const float* att = (const float*)d_in[4];
    const float* Wg  = (const float*)d_in[5];
    float* out = (float*)d_out;
    (void)in_sizes; (void)n_in; (void)out_size;

    k_zero_cnt<<<(N_NODES + 255) / 256, 256>>>();
    k_detect<<<1, 32>>>((const int*)ei);
    k_convert_hist<<<(E_EDGES + 255) / 256, 256>>>(ei);
    k_chunk_sum<<<(NCHUNK + 255) / 256, 256>>>();
    k_scan_chunks<<<1, SCAN_T>>>();
    k_fill_rowptr<<<(NCHUNK + 255) / 256, 256>>>();
    k_fill<<<(E_EDGES + 255) / 256, 256>>>();
    k_node_linear<<<1184, 256>>>(x, Wl, Wr);
    k_gat_node<<<(N_NODES + 7) / 8, 256>>>(att);
    k_gcn_node<<<(N_NODES + 7) / 8, 256>>>();
    k_out_linear<<<592, 128>>>(Wg, out);
}

// round 10
// speedup vs baseline: 7.8775x; 1.0296x over previous
#include <cuda_runtime.h>
#include <cuda_fp16.h>
#include <cstdint>

#define N_NODES 50000
#define E_EDGES 800000
#define NHEAD 4
#define C 64
#define DIN 32
#define DOUT 128
#define HC 256   // NHEAD * C

#define CHUNK 16
#define NCHUNK ((N_NODES + CHUNK - 1) / CHUNK)   // 3125

// ---------------- device scratch ----------------------------------------------------------
__device__ int    g_is64;
__device__ int    g_cnt[N_NODES];         // in-degree histogram
__device__ int    g_chunksum[NCHUNK];
__device__ int    g_chunkpre[NCHUNK];
__device__ int    g_rowptr[N_NODES + 1];  // CSR row pointers (by dst)
__device__ int    g_cursor[N_NODES];
__device__ int    g_csrc[E_EDGES];        // src node per CSR slot
__device__ __half g_xl[N_NODES * HC];     // fp16 storage, fp32 math
__device__ __half g_xr[N_NODES * HC];
__device__ float  g_h[N_NODES * C];       // dinv[n]*elu(head-mean), fp32 (2nd-hop accuracy)
__device__ float  g_agg[N_NODES * C];

// ---------------- helpers ------------------------------------------------------------------
__device__ __forceinline__ unsigned long long pack2(float lo, float hi) {
    unsigned long long r;
    asm("mov.b64 %0, {%1,%2};" : "=l"(r) : "f"(lo), "f"(hi));
    return r;
}
__device__ __forceinline__ unsigned long long fma2(unsigned long long a,
                                                   unsigned long long b,
                                                   unsigned long long c) {
    unsigned long long d;
    asm("fma.rn.f32x2 %0, %1, %2, %3;" : "=l"(d) : "l"(a), "l"(b), "l"(c));
    return d;
}
__device__ __forceinline__ float hsum2(unsigned long long v) {
    float lo, hi;
    asm("mov.b64 {%0,%1}, %2;" : "=f"(lo), "=f"(hi) : "l"(v));
    return lo + hi;
}
// load 4 consecutive halves as 4 floats
__device__ __forceinline__ float4 ldh4(const __half* p) {
    uint2 raw = *(const uint2*)p;
    __half2 h0 = *(__half2*)&raw.x;
    __half2 h1 = *(__half2*)&raw.y;
    float2 f0 = __half22float2(h0);
    float2 f1 = __half22float2(h1);
    return make_float4(f0.x, f0.y, f1.x, f1.y);
}

// ---------------- K0: zero histogram -------------------------------------------------------
__global__ void k_zero_cnt() {
    int i = blockIdx.x * blockDim.x + threadIdx.x;
    if (i < N_NODES) g_cnt[i] = 0;
}

// ---------------- K1: detect index dtype ---------------------------------------------------
__global__ void k_detect(const int* __restrict__ ei32) {
    if (threadIdx.x == 0 && blockIdx.x == 0) {
        int odd_zero = 1;
        for (int i = 1; i < 64; i += 2)
            if (ei32[i] != 0) { odd_zero = 0; break; }
        g_is64 = odd_zero;
    }
}

// ---------------- K2: degree histogram straight from ei ------------------------------------
__global__ void k_hist(const void* __restrict__ ei) {
    int e = blockIdx.x * blockDim.x + threadIdx.x;
    if (e >= E_EDGES) return;
    int d = g_is64 ? (int)((const long long*)ei)[E_EDGES + e]
                   : ((const int*)ei)[E_EDGES + e];
    atomicAdd(&g_cnt[d], 1);
}

// ---------------- K3a: per-chunk sums ------------------------------------------------------
__global__ void k_chunk_sum() {
    int c = blockIdx.x * blockDim.x + threadIdx.x;
    if (c >= NCHUNK) return;
    int b = c * CHUNK;
    int e = min(b + CHUNK, N_NODES);
    int s = 0;
    #pragma unroll 4
    for (int i = b; i < e; i++) s += g_cnt[i];
    g_chunksum[c] = s;
}

// ---------------- K3b: scan chunk sums in one block ----------------------------------------
#define SCAN_T 1024
#define PER_T  ((NCHUNK + SCAN_T - 1) / SCAN_T)   // 4
__global__ void __launch_bounds__(SCAN_T) k_scan_chunks() {
    __shared__ int part[SCAN_T];
    int t = threadIdx.x;
    int v[PER_T];
    int s = 0;
    #pragma unroll
    for (int j = 0; j < PER_T; j++) {
        int c = t * PER_T + j;
        v[j] = (c < NCHUNK) ? g_chunksum[c] : 0;
        s += v[j];
    }
    part[t] = s;
    __syncthreads();
    for (int off = 1; off < SCAN_T; off <<= 1) {
        int u = (t >= off) ? part[t - off] : 0;
        __syncthreads();
        part[t] += u;
        __syncthreads();
    }
    int pre = (t == 0) ? 0 : part[t - 1];
    #pragma unroll
    for (int j = 0; j < PER_T; j++) {
        int c = t * PER_T + j;
        if (c < NCHUNK) g_chunkpre[c] = pre;
        pre += v[j];
    }
    if (t == SCAN_T - 1) g_rowptr[N_NODES] = part[SCAN_T - 1];
}

// ---------------- K3c: expand rowptr/cursor ------------------------------------------------
__global__ void k_fill_rowptr() {
    int c = blockIdx.x * blockDim.x + threadIdx.x;
    if (c >= NCHUNK) return;
    int b = c * CHUNK;
    int e = min(b + CHUNK, N_NODES);
    int pre = g_chunkpre[c];
    for (int i = b; i < e; i++) {
        g_rowptr[i] = pre;
        g_cursor[i] = pre;
        pre += g_cnt[i];
    }
}

// ---------------- K4: CSR fill straight from ei --------------------------------------------
__global__ void k_fill(const void* __restrict__ ei) {
    int e = blockIdx.x * blockDim.x + threadIdx.x;
    if (e >= E_EDGES) return;
    int s, d;
    if (g_is64) {
        const long long* p = (const long long*)ei;
        s = (int)p[e];
        d = (int)p[E_EDGES + e];
    } else {
        const int* p = (const int*)ei;
        s = p[e];
        d = p[E_EDGES + e];
    }
    int pos = atomicAdd(&g_cursor[d], 1);
    g_csrc[pos] = s;
}

// ---------------- K5: node linear (f32x2, dual accumulator chains, fp16 stores) ------------
#define NL_TILE 16
__global__ void __launch_bounds__(256, 2) k_node_linear(const float* __restrict__ x,
                                                        const float* __restrict__ Wl,
                                                        const float* __restrict__ Wr) {
    __shared__ float sw[256 * 33];
    __shared__ float sx[NL_TILE * DIN];
    int o = threadIdx.x;
    unsigned long long wl[DIN / 2], wr[DIN / 2];
    for (int i = threadIdx.x; i < 256 * DIN; i += 256)
        sw[(i >> 5) * 33 + (i & 31)] = Wl[i];
    __syncthreads();
    #pragma unroll
    for (int k = 0; k < DIN / 2; k++) wl[k] = pack2(sw[o * 33 + 2 * k], sw[o * 33 + 2 * k + 1]);
    __syncthreads();
    for (int i = threadIdx.x; i < 256 * DIN; i += 256)
        sw[(i >> 5) * 33 + (i & 31)] = Wr[i];
    __syncthreads();
    #pragma unroll
    for (int k = 0; k < DIN / 2; k++) wr[k] = pack2(sw[o * 33 + 2 * k], sw[o * 33 + 2 * k + 1]);

    for (int base = blockIdx.x * NL_TILE; base < N_NODES; base += gridDim.x * NL_TILE) {
        int nn = min(NL_TILE, N_NODES - base);
        __syncthreads();
        for (int i = threadIdx.x; i < nn * DIN; i += 256)
            sx[i] = x[base * DIN + i];
        __syncthreads();
        for (int j = 0; j < nn; j++) {
            const unsigned long long* sxp = (const unsigned long long*)(sx + j * DIN);
            unsigned long long alA = 0, alB = 0, arA = 0, arB = 0;  // dual chains -> 2x ILP
            #pragma unroll
            for (int k = 0; k < DIN / 2; k += 2) {
                unsigned long long xv0 = sxp[k], xv1 = sxp[k + 1];
                alA = fma2(wl[k],     xv0, alA);
                alB = fma2(wl[k + 1], xv1, alB);
                arA = fma2(wr[k],     xv0, arA);
                arB = fma2(wr[k + 1], xv1, arB);
            }
            g_xl[(size_t)(base + j) * HC + o] = __float2half(hsum2(alA) + hsum2(alB));
            g_xr[(size_t)(base + j) * HC + o] = __float2half(hsum2(arA) + hsum2(arB));
        }
    }
}

// ---------------- K6: node-centric fused GAT (fp16 gathers, 2-edge unroll) -----------------
__global__ void __launch_bounds__(256) k_gat_node(const float* __restrict__ att) {
    __shared__ float satt[HC];
    if (threadIdx.x < HC) satt[threadIdx.x] = att[threadIdx.x];
    __syncthreads();
    int n = blockIdx.x * 8 + (threadIdx.x >> 5);
    if (n >= N_NODES) return;
    int l = threadIdx.x & 31;
    int beg = g_rowptr[n], end = g_rowptr[n + 1];

    const __half* xr_row = g_xr + (size_t)n * HC;
    float4 b0 = ldh4(xr_row + 4 * l);
    float4 b1 = ldh4(xr_row + 128 + 4 * l);
    float t0x = satt[4*l+0], t0y = satt[4*l+1], t0z = satt[4*l+2], t0w = satt[4*l+3];
    float t1x = satt[128+4*l+0], t1y = satt[128+4*l+1], t1z = satt[128+4*l+2], t1w = satt[128+4*l+3];

    float4 acc0 = {0.f,0.f,0.f,0.f}, acc1 = {0.f,0.f,0.f,0.f};
    float den0 = 0.f, den1 = 0.f;

    #define GAT_LOGIT(a0, a1, p0, p1) do {                                  \
        float v;                                                            \
        v = a0.x + b0.x; v = v > 0.f ? v : 0.2f * v; p0 += v * t0x;         \
        v = a0.y + b0.y; v = v > 0.f ? v : 0.2f * v; p0 += v * t0y;         \
        v = a0.z + b0.z; v = v > 0.f ? v : 0.2f * v; p0 += v * t0z;         \
        v = a0.w + b0.w; v = v > 0.f ? v : 0.2f * v; p0 += v * t0w;         \
        v = a1.x + b1.x; v = v > 0.f ? v : 0.2f * v; p1 += v * t1x;         \
        v = a1.y + b1.y; v = v > 0.f ? v : 0.2f * v; p1 += v * t1y;         \
        v = a1.z + b1.z; v = v > 0.f ? v : 0.2f * v; p1 += v * t1z;         \
        v = a1.w + b1.w; v = v > 0.f ? v : 0.2f * v; p1 += v * t1w;         \
    } while (0)

    int i = beg;
    for (; i + 1 < end; i += 2) {
        int srcA = __ldg(&g_csrc[i]);
        int srcB = __ldg(&g_csrc[i + 1]);
        const __half* plA = g_xl + (size_t)srcA * HC;
        const __half* plB = g_xl + (size_t)srcB * HC;
        float4 a0A = ldh4(plA + 4 * l), a1A = ldh4(plA + 128 + 4 * l);
        float4 a0B = ldh4(plB + 4 * l), a1B = ldh4(plB + 128 + 4 * l);
        float p0A = 0.f, p1A = 0.f, p0B = 0.f, p1B = 0.f;
        GAT_LOGIT(a0A, a1A, p0A, p1A);
        GAT_LOGIT(a0B, a1B, p0B, p1B);
        #pragma unroll
        for (int s = 8; s >= 1; s >>= 1) {   // interleaved chains: 2x ILP on SHFL
            p0A += __shfl_xor_sync(0xffffffffu, p0A, s);
            p1A += __shfl_xor_sync(0xffffffffu, p1A, s);
            p0B += __shfl_xor_sync(0xffffffffu, p0B, s);
            p1B += __shfl_xor_sync(0xffffffffu, p1B, s);
        }
        float ex0A = __expf(p0A), ex1A = __expf(p1A);
        float ex0B = __expf(p0B), ex1B = __expf(p1B);
        acc0.x += a0A.x * ex0A + a0B.x * ex0B;
        acc0.y += a0A.y * ex0A + a0B.y * ex0B;
        acc0.z += a0A.z * ex0A + a0B.z * ex0B;
        acc0.w += a0A.w * ex0A + a0B.w * ex0B;
        acc1.x += a1A.x * ex1A + a1B.x * ex1B;
        acc1.y += a1A.y * ex1A + a1B.y * ex1B;
        acc1.z += a1A.z * ex1A + a1B.z * ex1B;
        acc1.w += a1A.w * ex1A + a1B.w * ex1B;
        den0 += ex0A + ex0B;
        den1 += ex1A + ex1B;
    }
    if (i < end) {
        int src = __ldg(&g_csrc[i]);
        const __half* pl = g_xl + (size_t)src * HC;
        float4 a0 = ldh4(pl + 4 * l), a1 = ldh4(pl + 128 + 4 * l);
        float p0 = 0.f, p1 = 0.f;
        GAT_LOGIT(a0, a1, p0, p1);
        #pragma unroll
        for (int s = 8; s >= 1; s >>= 1) {
            p0 += __shfl_xor_sync(0xffffffffu, p0, s);
            p1 += __shfl_xor_sync(0xffffffffu, p1, s);
        }
        float ex0 = __expf(p0), ex1 = __expf(p1);
        acc0.x += a0.x * ex0; acc0.y += a0.y * ex0; acc0.z += a0.z * ex0; acc0.w += a0.w * ex0;
        acc1.x += a1.x * ex1; acc1.y += a1.y * ex1; acc1.z += a1.z * ex1; acc1.w += a1.w * ex1;
        den0 += ex0; den1 += ex1;
    }
    #undef GAT_LOGIT

    float inv0 = 1.0f / (den0 + 1e-16f);
    float inv1 = 1.0f / (den1 + 1e-16f);
    float sx = acc0.x * inv0 + acc1.x * inv1;
    float sy = acc0.y * inv0 + acc1.y * inv1;
    float sz = acc0.z * inv0 + acc1.z * inv1;
    float sw = acc0.w * inv0 + acc1.w * inv1;
    sx += __shfl_xor_sync(0xffffffffu, sx, 16);
    sy += __shfl_xor_sync(0xffffffffu, sy, 16);
    sz += __shfl_xor_sync(0xffffffffu, sz, 16);
    sw += __shfl_xor_sync(0xffffffffu, sw, 16);
    if (l < 16) {
        float deg = (float)(end - beg);
        float dinv = deg > 0.f ? rsqrtf(deg) : 0.f;
        float4 o;
        float m;
        m = 0.25f * sx; m = m > 0.f ? m : expm1f(m); o.x = m * dinv;
        m = 0.25f * sy; m = m > 0.f ? m : expm1f(m); o.y = m * dinv;
        m = 0.25f * sz; m = m > 0.f ? m : expm1f(m); o.z = m * dinv;
        m = 0.25f * sw; m = m > 0.f ? m : expm1f(m); o.w = m * dinv;
        ((float4*)(g_h + (size_t)n * C))[l] = o;
    }
}

// ---------------- K7: node-centric GCN aggregate -------------------------------------------
__global__ void __launch_bounds__(256) k_gcn_node() {
    int n = blockIdx.x * 8 + (threadIdx.x >> 5);
    if (n >= N_NODES) return;
    int l = threadIdx.x & 31;
    int beg = g_rowptr[n], end = g_rowptr[n + 1];
    float ax = 0.f, ay = 0.f;
    for (int i = beg; i < end; i++) {
        int src = __ldg(&g_csrc[i]);
        float2 v = ((const float2*)(g_h + (size_t)src * C))[l];
        ax += v.x; ay += v.y;
    }
    float deg = (float)(end - beg);
    float dinv = deg > 0.f ? rsqrtf(deg) : 0.f;
    float2 o; o.x = ax * dinv; o.y = ay * dinv;
    ((float2*)(g_agg + (size_t)n * C))[l] = o;
}

// ---------------- K8: final linear (f32x2) -------------------------------------------------
#define OL_TILE 8
__global__ void __launch_bounds__(128) k_out_linear(const float* __restrict__ Wg,
                                                    float* __restrict__ out) {
    __shared__ float sw[DOUT * 65];
    __shared__ float sh[OL_TILE * C];
    int o = threadIdx.x;
    unsigned long long wg[C / 2];
    for (int i = threadIdx.x; i < DOUT * C; i += 128)
        sw[(i >> 6) * 65 + (i & 63)] = Wg[i];
    __syncthreads();
    #pragma unroll
    for (int k = 0; k < C / 2; k++) wg[k] = pack2(sw[o * 65 + 2 * k], sw[o * 65 + 2 * k + 1]);

    for (int base = blockIdx.x * OL_TILE; base < N_NODES; base += gridDim.x * OL_TILE) {
        int nn = min(OL_TILE, N_NODES - base);
        __syncthreads();
        for (int i = threadIdx.x; i < nn * C; i += 128)
            sh[i] = g_agg[(size_t)base * C + i];
        __syncthreads();
        for (int j = 0; j < nn; j++) {
            const unsigned long long* shp = (const unsigned long long*)(sh + j * C);
            unsigned long long s2 = 0;
            #pragma unroll
            for (int k = 0; k < C / 2; k++)
                s2 = fma2(wg[k], shp[k], s2);
            out[(size_t)(base + j) * DOUT + o] = hsum2(s2);
        }
    }
}

// ---------------- launch -------------------------------------------------------------------
extern "C" void kernel_launch(void* const* d_in, const int* in_sizes, int n_in,
                              void* d_out, int out_size) {
    const float* x   = (const float*)d_in[0];
    const void*  ei  = d_in[1];
    const float* Wl  = (const float*)d_in[2];
    const float* Wr  = (const float*)d_in[3];
    const float* att = (const float*)d_in[4];
    const float* Wg  = (const float*)d_in[5];
    float* out = (float*)d_out;
    (void)in_sizes; (void)n_in; (void)out_size;

    k_zero_cnt<<<(N_NODES + 255) / 256, 256>>>();
    k_detect<<<1, 32>>>((const int*)ei);
    k_hist<<<(E_EDGES + 255) / 256, 256>>>(ei);
    k_chunk_sum<<<(NCHUNK + 255) / 256, 256>>>();
    k_scan_chunks<<<1, SCAN_T>>>();
    k_fill_rowptr<<<(NCHUNK + 255) / 256, 256>>>();
    k_fill<<<(E_EDGES + 255) / 256, 256>>>(ei);
    k_node_linear<<<1184, 256>>>(x, Wl, Wr);
    k_gat_node<<<(N_NODES + 7) / 8, 256>>>(att);
    k_gcn_node<<<(N_NODES + 7) / 8, 256>>>();
    k_out_linear<<<592, 128>>>(Wg, out);
}

// round 13
// speedup vs baseline: 8.2556x; 1.0480x over previous
#include <cuda_runtime.h>
#include <cuda_fp16.h>
#include <cstdint>

#define N_NODES 50000
#define E_EDGES 800000
#define NHEAD 4
#define C 64
#define DIN 32
#define DOUT 128
#define HC 256   // NHEAD * C

#define CHUNK 16
#define NCHUNK ((N_NODES + CHUNK - 1) / CHUNK)   // 3125

// ---------------- device scratch ----------------------------------------------------------
__device__ int    g_is64;
__device__ int    g_cnt[N_NODES];
__device__ int    g_chunksum[NCHUNK];
__device__ int    g_chunkpre[NCHUNK];
__device__ int    g_rowptr[N_NODES + 1];
__device__ int    g_cursor[N_NODES];
__device__ int    g_csrc[E_EDGES];
__device__ __half g_xl[N_NODES * HC];     // fp16 storage, fp32 math
__device__ __half g_xr[N_NODES * HC];
__device__ float  g_h[N_NODES * C];
__device__ float  g_agg[N_NODES * C];

// ---------------- helpers ------------------------------------------------------------------
__device__ __forceinline__ unsigned long long pack2(float lo, float hi) {
    unsigned long long r;
    asm("mov.b64 %0, {%1,%2};" : "=l"(r) : "f"(lo), "f"(hi));
    return r;
}
__device__ __forceinline__ unsigned long long fma2(unsigned long long a,
                                                   unsigned long long b,
                                                   unsigned long long c) {
    unsigned long long d;
    asm("fma.rn.f32x2 %0, %1, %2, %3;" : "=l"(d) : "l"(a), "l"(b), "l"(c));
    return d;
}
__device__ __forceinline__ float hsum2(unsigned long long v) {
    float lo, hi;
    asm("mov.b64 {%0,%1}, %2;" : "=f"(lo), "=f"(hi) : "l"(v));
    return lo + hi;
}
// 8 consecutive halves (16B aligned) -> two float4, by value (registerizable)
struct F8 { float4 lo, hi; };
__device__ __forceinline__ F8 ldh8(const __half* p) {
    uint4 raw = *(const uint4*)p;
    const __half2* h = (const __half2*)&raw;
    float2 f0 = __half22float2(h[0]);
    float2 f1 = __half22float2(h[1]);
    float2 f2 = __half22float2(h[2]);
    float2 f3 = __half22float2(h[3]);
    F8 r;
    r.lo = make_float4(f0.x, f0.y, f1.x, f1.y);
    r.hi = make_float4(f2.x, f2.y, f3.x, f3.y);
    return r;
}

// ---------------- K0: zero histogram + detect dtype (fused) --------------------------------
__global__ void k_zero_cnt(const int* __restrict__ ei32) {
    int i = blockIdx.x * blockDim.x + threadIdx.x;
    if (i < N_NODES) g_cnt[i] = 0;
    if (i == 0) {
        int odd_zero = 1;
        for (int j = 1; j < 64; j += 2)
            if (ei32[j] != 0) { odd_zero = 0; break; }
        g_is64 = odd_zero;   // int64 viewed as int32: odd positions all zero
    }
}

// ---------------- K1: degree histogram straight from ei ------------------------------------
__global__ void k_hist(const void* __restrict__ ei) {
    int e = blockIdx.x * blockDim.x + threadIdx.x;
    if (e >= E_EDGES) return;
    int d = g_is64 ? (int)((const long long*)ei)[E_EDGES + e]
                   : ((const int*)ei)[E_EDGES + e];
    atomicAdd(&g_cnt[d], 1);
}

// ---------------- K2a: per-chunk sums ------------------------------------------------------
__global__ void k_chunk_sum() {
    int c = blockIdx.x * blockDim.x + threadIdx.x;
    if (c >= NCHUNK) return;
    int b = c * CHUNK;
    int e = min(b + CHUNK, N_NODES);
    int s = 0;
    #pragma unroll 4
    for (int i = b; i < e; i++) s += g_cnt[i];
    g_chunksum[c] = s;
}

// ---------------- K2b: scan chunk sums in one block ----------------------------------------
#define SCAN_T 1024
#define PER_T  ((NCHUNK + SCAN_T - 1) / SCAN_T)   // 4
__global__ void __launch_bounds__(SCAN_T) k_scan_chunks() {
    __shared__ int part[SCAN_T];
    int t = threadIdx.x;
    int v[PER_T];
    int s = 0;
    #pragma unroll
    for (int j = 0; j < PER_T; j++) {
        int c = t * PER_T + j;
        v[j] = (c < NCHUNK) ? g_chunksum[c] : 0;
        s += v[j];
    }
    part[t] = s;
    __syncthreads();
    for (int off = 1; off < SCAN_T; off <<= 1) {
        int u = (t >= off) ? part[t - off] : 0;
        __syncthreads();
        part[t] += u;
        __syncthreads();
    }
    int pre = (t == 0) ? 0 : part[t - 1];
    #pragma unroll
    for (int j = 0; j < PER_T; j++) {
        int c = t * PER_T + j;
        if (c < NCHUNK) g_chunkpre[c] = pre;
        pre += v[j];
    }
    if (t == SCAN_T - 1) g_rowptr[N_NODES] = part[SCAN_T - 1];
}

// ---------------- K2c: expand rowptr/cursor ------------------------------------------------
__global__ void k_fill_rowptr() {
    int c = blockIdx.x * blockDim.x + threadIdx.x;
    if (c >= NCHUNK) return;
    int b = c * CHUNK;
    int e = min(b + CHUNK, N_NODES);
    int pre = g_chunkpre[c];
    for (int i = b; i < e; i++) {
        g_rowptr[i] = pre;
        g_cursor[i] = pre;
        pre += g_cnt[i];
    }
}

// ---------------- K3: CSR fill straight from ei --------------------------------------------
__global__ void k_fill(const void* __restrict__ ei) {
    int e = blockIdx.x * blockDim.x + threadIdx.x;
    if (e >= E_EDGES) return;
    int s, d;
    if (g_is64) {
        const long long* p = (const long long*)ei;
        s = (int)p[e];
        d = (int)p[E_EDGES + e];
    } else {
        const int* p = (const int*)ei;
        s = p[e];
        d = p[E_EDGES + e];
    }
    int pos = atomicAdd(&g_cursor[d], 1);
    g_csrc[pos] = s;
}

// ---------------- K4: node linear, one matrix per launch; dst selected IN DEVICE CODE ------
#define NL_TILE 16
__global__ void __launch_bounds__(256) k_node_linear_one(const float* __restrict__ x,
                                                         const float* __restrict__ W,
                                                         int which) {
    __half* outh = which ? g_xr : g_xl;   // device-side global selection (no host symbol!)
    __shared__ float sw[256 * 33];
    __shared__ float sx[NL_TILE * DIN];
    int o = threadIdx.x;
    unsigned long long w[DIN / 2];
    for (int i = threadIdx.x; i < 256 * DIN; i += 256)
        sw[(i >> 5) * 33 + (i & 31)] = W[i];
    __syncthreads();
    #pragma unroll
    for (int k = 0; k < DIN / 2; k++) w[k] = pack2(sw[o * 33 + 2 * k], sw[o * 33 + 2 * k + 1]);

    for (int base = blockIdx.x * NL_TILE; base < N_NODES; base += gridDim.x * NL_TILE) {
        int nn = min(NL_TILE, N_NODES - base);
        __syncthreads();
        for (int i = threadIdx.x; i < nn * DIN; i += 256)
            sx[i] = x[base * DIN + i];
        __syncthreads();
        for (int j = 0; j < nn; j++) {
            const unsigned long long* sxp = (const unsigned long long*)(sx + j * DIN);
            unsigned long long aA = 0, aB = 0;
            #pragma unroll
            for (int k = 0; k < DIN / 2; k += 2) {
                aA = fma2(w[k],     sxp[k],     aA);
                aB = fma2(w[k + 1], sxp[k + 1], aB);
            }
            outh[(size_t)(base + j) * HC + o] = __float2half(hsum2(aA) + hsum2(aB));
        }
    }
}

// ---------------- K5: node-centric fused GAT (head-per-8-lane) -----------------------------
// Warp per dst node. Lane l: head h = l>>3, channels [8g, 8g+8), g = l&7.
// Per edge: 1 uint4 gather, 8 FMA logit, 3 shuffles, 1 exp, 8 FMA accumulate.
__global__ void __launch_bounds__(256) k_gat_node(const float* __restrict__ att) {
    __shared__ float satt[HC];
    if (threadIdx.x < HC) satt[threadIdx.x] = att[threadIdx.x];
    __syncthreads();
    int n = blockIdx.x * 8 + (threadIdx.x >> 5);
    if (n >= N_NODES) return;
    int l = threadIdx.x & 31;
    int h = l >> 3, g = l & 7;
    int off = h * C + 8 * g;
    int beg = g_rowptr[n], end = g_rowptr[n + 1];

    F8 b = ldh8(g_xr + (size_t)n * HC + off);
    float4 tlo = *(const float4*)(satt + off);
    float4 thi = *(const float4*)(satt + off + 4);

    float4 acc_lo = {0.f,0.f,0.f,0.f}, acc_hi = {0.f,0.f,0.f,0.f};
    float den = 0.f;

    #define GAT_LOGIT8(A, P) do {                                              \
        float v_;                                                              \
        v_ = A.lo.x + b.lo.x; v_ = v_ > 0.f ? v_ : 0.2f * v_; P += v_ * tlo.x; \
        v_ = A.lo.y + b.lo.y; v_ = v_ > 0.f ? v_ : 0.2f * v_; P += v_ * tlo.y; \
        v_ = A.lo.z + b.lo.z; v_ = v_ > 0.f ? v_ : 0.2f * v_; P += v_ * tlo.z; \
        v_ = A.lo.w + b.lo.w; v_ = v_ > 0.f ? v_ : 0.2f * v_; P += v_ * tlo.w; \
        v_ = A.hi.x + b.hi.x; v_ = v_ > 0.f ? v_ : 0.2f * v_; P += v_ * thi.x; \
        v_ = A.hi.y + b.hi.y; v_ = v_ > 0.f ? v_ : 0.2f * v_; P += v_ * thi.y; \
        v_ = A.hi.z + b.hi.z; v_ = v_ > 0.f ? v_ : 0.2f * v_; P += v_ * thi.z; \
        v_ = A.hi.w + b.hi.w; v_ = v_ > 0.f ? v_ : 0.2f * v_; P += v_ * thi.w; \
    } while (0)

    #define GAT_ACCUM8(A, EX) do {                                           \
        acc_lo.x += A.lo.x * EX; acc_lo.y += A.lo.y * EX;                    \
        acc_lo.z += A.lo.z * EX; acc_lo.w += A.lo.w * EX;                    \
        acc_hi.x += A.hi.x * EX; acc_hi.y += A.hi.y * EX;                    \
        acc_hi.z += A.hi.z * EX; acc_hi.w += A.hi.w * EX;                    \
    } while (0)

    int i = beg;
    for (; i + 1 < end; i += 2) {
        int srcA = __ldg(&g_csrc[i]);
        int srcB = __ldg(&g_csrc[i + 1]);
        F8 aA = ldh8(g_xl + (size_t)srcA * HC + off);
        F8 aB = ldh8(g_xl + (size_t)srcB * HC + off);
        float pA = 0.f, pB = 0.f;
        GAT_LOGIT8(aA, pA);
        GAT_LOGIT8(aB, pB);
        #pragma unroll
        for (int s = 4; s >= 1; s >>= 1) {
            pA += __shfl_xor_sync(0xffffffffu, pA, s);
            pB += __shfl_xor_sync(0xffffffffu, pB, s);
        }
        float exA = __expf(pA), exB = __expf(pB);
        GAT_ACCUM8(aA, exA);
        GAT_ACCUM8(aB, exB);
        den += exA + exB;
    }
    if (i < end) {
        int src = __ldg(&g_csrc[i]);
        F8 a = ldh8(g_xl + (size_t)src * HC + off);
        float p = 0.f;
        GAT_LOGIT8(a, p);
        #pragma unroll
        for (int s = 4; s >= 1; s >>= 1)
            p += __shfl_xor_sync(0xffffffffu, p, s);
        float ex = __expf(p);
        GAT_ACCUM8(a, ex);
        den += ex;
    }
    #undef GAT_LOGIT8
    #undef GAT_ACCUM8

    // normalize by this head's denom, then sum heads across lanes g, 8+g, 16+g, 24+g
    float inv = 1.0f / (den + 1e-16f);
    #define HEADSUM(F) do {                                                  \
        F *= inv;                                                            \
        F += __shfl_xor_sync(0xffffffffu, F, 8);                             \
        F += __shfl_xor_sync(0xffffffffu, F, 16);                            \
    } while (0)
    HEADSUM(acc_lo.x); HEADSUM(acc_lo.y); HEADSUM(acc_lo.z); HEADSUM(acc_lo.w);
    HEADSUM(acc_hi.x); HEADSUM(acc_hi.y); HEADSUM(acc_hi.z); HEADSUM(acc_hi.w);
    #undef HEADSUM

    if (l < 8) {                                 // lanes 0..7 write channels 8l..8l+8
        float deg = (float)(end - beg);
        float dinv = deg > 0.f ? rsqrtf(deg) : 0.f;
        float4 o0, o1;
        float m;
        m = 0.25f * acc_lo.x; m = m > 0.f ? m : expm1f(m); o0.x = m * dinv;
        m = 0.25f * acc_lo.y; m = m > 0.f ? m : expm1f(m); o0.y = m * dinv;
        m = 0.25f * acc_lo.z; m = m > 0.f ? m : expm1f(m); o0.z = m * dinv;
        m = 0.25f * acc_lo.w; m = m > 0.f ? m : expm1f(m); o0.w = m * dinv;
        m = 0.25f * acc_hi.x; m = m > 0.f ? m : expm1f(m); o1.x = m * dinv;
        m = 0.25f * acc_hi.y; m = m > 0.f ? m : expm1f(m); o1.y = m * dinv;
        m = 0.25f * acc_hi.z; m = m > 0.f ? m : expm1f(m); o1.z = m * dinv;
        m = 0.25f * acc_hi.w; m = m > 0.f ? m : expm1f(m); o1.w = m * dinv;
        float4* dst = (float4*)(g_h + (size_t)n * C + 8 * l);
        dst[0] = o0;
        dst[1] = o1;
    }
}

// ---------------- K6: node-centric GCN aggregate (2-edge unroll) ---------------------------
__global__ void __launch_bounds__(256) k_gcn_node() {
    int n = blockIdx.x * 8 + (threadIdx.x >> 5);
    if (n >= N_NODES) return;
    int l = threadIdx.x & 31;
    int beg = g_rowptr[n], end = g_rowptr[n + 1];
    float ax = 0.f, ay = 0.f;
    int i = beg;
    for (; i + 1 < end; i += 2) {
        int srcA = __ldg(&g_csrc[i]);
        int srcB = __ldg(&g_csrc[i + 1]);
        float2 vA = ((const float2*)(g_h + (size_t)srcA * C))[l];
        float2 vB = ((const float2*)(g_h + (size_t)srcB * C))[l];
        ax += vA.x + vB.x; ay += vA.y + vB.y;
    }
    if (i < end) {
        int src = __ldg(&g_csrc[i]);
        float2 v = ((const float2*)(g_h + (size_t)src * C))[l];
        ax += v.x; ay += v.y;
    }
    float deg = (float)(end - beg);
    float dinv = deg > 0.f ? rsqrtf(deg) : 0.f;
    float2 o; o.x = ax * dinv; o.y = ay * dinv;
    ((float2*)(g_agg + (size_t)n * C))[l] = o;
}

// ---------------- K7: final linear (f32x2) -------------------------------------------------
#define OL_TILE 8
__global__ void __launch_bounds__(128) k_out_linear(const float* __restrict__ Wg,
                                                    float* __restrict__ out) {
    __shared__ float sw[DOUT * 65];
    __shared__ float sh[OL_TILE * C];
    int o = threadIdx.x;
    unsigned long long wg[C / 2];
    for (int i = threadIdx.x; i < DOUT * C; i += 128)
        sw[(i >> 6) * 65 + (i & 63)] = Wg[i];
    __syncthreads();
    #pragma unroll
    for (int k = 0; k < C / 2; k++) wg[k] = pack2(sw[o * 65 + 2 * k], sw[o * 65 + 2 * k + 1]);

    for (int base = blockIdx.x * OL_TILE; base < N_NODES; base += gridDim.x * OL_TILE) {
        int nn = min(OL_TILE, N_NODES - base);
        __syncthreads();
        for (int i = threadIdx.x; i < nn * C; i += 128)
            sh[i] = g_agg[(size_t)base * C + i];
        __syncthreads();
        for (int j = 0; j < nn; j++) {
            const unsigned long long* shp = (const unsigned long long*)(sh + j * C);
            unsigned long long sA = 0, sB = 0;
            #pragma unroll
            for (int k = 0; k < C / 2; k += 2) {
                sA = fma2(wg[k],     shp[k],     sA);
                sB = fma2(wg[k + 1], shp[k + 1], sB);
            }
            out[(size_t)(base + j) * DOUT + o] = hsum2(sA) + hsum2(sB);
        }
    }
}

// ---------------- launch -------------------------------------------------------------------
extern "C" void kernel_launch(void* const* d_in, const int* in_sizes, int n_in,
                              void* d_out, int out_size) {
    const float* x   = (const float*)d_in[0];
    const void*  ei  = d_in[1];
    const float* Wl  = (const float*)d_in[2];
    const float* Wr  = (const float*)d_in[3];
    const float* att = (const float*)d_in[4];
    const float* Wg  = (const float*)d_in[5];
    float* out = (float*)d_out;
    (void)in_sizes; (void)n_in; (void)out_size;

    k_zero_cnt<<<(N_NODES + 255) / 256, 256>>>((const int*)ei);
    k_hist<<<(E_EDGES + 255) / 256, 256>>>(ei);
    k_chunk_sum<<<(NCHUNK + 255) / 256, 256>>>();
    k_scan_chunks<<<1, SCAN_T>>>();
    k_fill_rowptr<<<(NCHUNK + 255) / 256, 256>>>();
    k_fill<<<(E_EDGES + 255) / 256, 256>>>(ei);
    k_node_linear_one<<<1184, 256>>>(x, Wl, 0);
    k_node_linear_one<<<1184, 256>>>(x, Wr, 1);
    k_gat_node<<<(N_NODES + 7) / 8, 256>>>(att);
    k_gcn_node<<<(N_NODES + 7) / 8, 256>>>();
    k_out_linear<<<592, 128>>>(Wg, out);
}